// round 4
// baseline (speedup 1.0000x reference)
#include <cuda_runtime.h>
#include <math.h>

#define DD   128
#define DV4  32
#define NH   4
#define GMAX 64
#define NMAX 100000
#define EMAX 500000
#define SMEM_GEMM ((16384 + 128*68)*4)

// ---------------- device scratch (static, no allocation) ----------------
__device__ float g_feat[NMAX*DD];
__device__ float g_q[NMAX*DD];
__device__ float g_k[NMAX*DD];
__device__ float g_v[NMAX*DD];
__device__ float g_agg[NMAX*DD];
__device__ float g_P1[NMAX*DD];
__device__ float g_P2[NMAX*DD];
__device__ float g_e[EMAX*DD];
__device__ float g_ek[EMAX*DD];
__device__ float g_ev[EMAX*DD];
__device__ float g_sc[EMAX*NH];
__device__ float g_m[NMAX*NH];
__device__ float g_den[NMAX*NH];
__device__ int   g_cnt[NMAX];
__device__ int   g_rowptr[NMAX+1];
__device__ int   g_eid[EMAX];
__device__ float g_gagg[GMAX*DD];
__device__ float g_eagg[GMAX*DD];
__device__ float g_gcnt[GMAX];
__device__ float g_ecnt[GMAX];

// ---------------- small helpers ----------------
static inline int ceil_div(int a, int b) { return (a + b - 1) / b; }

__device__ __forceinline__ unsigned long long pack2(float x) {
    unsigned long long r;
    asm("mov.b64 %0, {%1, %1};" : "=l"(r) : "f"(x));
    return r;
}
#define FMA2(d, a, b) asm("fma.rn.f32x2 %0, %1, %2, %0;" : "+l"(d) : "l"(a), "l"(b))

// ---------------- setup kernels ----------------
__global__ void zero_cnt_k(int N) {
    int i = blockIdx.x * blockDim.x + threadIdx.x;
    if (i < N) g_cnt[i] = 0;
}

__global__ void hist_k(const int* __restrict__ dst, int E) {
    int i = blockIdx.x * blockDim.x + threadIdx.x;
    if (i < E) atomicAdd(&g_cnt[dst[i]], 1);
}

__global__ void scan_k(int N) {   // single block, 1024 threads
    __shared__ int sh[1024];
    __shared__ int carry_s;
    int t = threadIdx.x;
    if (t == 0) carry_s = 0;
    __syncthreads();
    for (int base = 0; base < N; base += 1024) {
        int v = (base + t < N) ? g_cnt[base + t] : 0;
        sh[t] = v;
        __syncthreads();
        for (int off = 1; off < 1024; off <<= 1) {
            int tmp = (t >= off) ? sh[t - off] : 0;
            __syncthreads();
            sh[t] += tmp;
            __syncthreads();
        }
        if (base + t < N) g_rowptr[base + t] = carry_s + sh[t] - v;
        __syncthreads();
        if (t == 0) carry_s += sh[1023];
        __syncthreads();
    }
    if (t == 0) g_rowptr[N] = carry_s;
}

__global__ void fill_k(const int* __restrict__ dst, int E) {
    int i = blockIdx.x * blockDim.x + threadIdx.x;
    if (i >= E) return;
    int d = dst[i];
    int slot = atomicAdd(&g_cnt[d], 1);
    g_eid[g_rowptr[d] + slot] = i;
}

__global__ void embed_k(const int* __restrict__ x, const float* __restrict__ emb, int n32) {
    int i = blockIdx.x * blockDim.x + threadIdx.x;
    if (i >= n32) return;
    int n = i >> 5, c = i & 31;
    ((float4*)g_feat)[i] = ((const float4*)emb)[(size_t)x[n] * DV4 + c];
}

__global__ void edge_enc_k(const int* __restrict__ flow, const int* __restrict__ pos,
                           const int* __restrict__ blk, const int* __restrict__ src,
                           const int* __restrict__ dst,
                           const float* __restrict__ fe, const float* __restrict__ pe,
                           const float* __restrict__ be, int e32) {
    int i = blockIdx.x * blockDim.x + threadIdx.x;
    if (i >= e32) return;
    int ed = i >> 5, c = i & 31;
    int cr = (blk[src[ed]] != blk[dst[ed]]) ? 1 : 0;
    float4 a = ((const float4*)fe)[flow[ed] * DV4 + c];
    float4 b = ((const float4*)pe)[pos[ed] * DV4 + c];
    float4 d = ((const float4*)be)[cr * DV4 + c];
    float4 o;
    o.x = a.x + b.x + d.x; o.y = a.y + b.y + d.y;
    o.z = a.z + b.z + d.z; o.w = a.w + b.w + d.w;
    ((float4*)g_e)[i] = o;
}

// ---------------- GEMM: C[M,128] = A[M,128] @ W[128,128] (+epilogue) -----------
// mode 0: C = A@W
// mode 1: C = relu(R + A@W)
// mode 2: C = relu(R + A@W + P1[sidx[row]] + P2[didx[row]])
__device__ __forceinline__ void emit_row(float* C, int mode, const float* R,
                                         const float* P1, const float* P2,
                                         const int* sidx, const int* didx,
                                         int r, int cg, int M,
                                         float x, float y, float z, float w) {
    if (r >= M) return;
    if (mode) {
        float4 res = ((const float4*)R)[(size_t)r * DV4 + cg];
        x += res.x; y += res.y; z += res.z; w += res.w;
        if (mode == 2) {
            int s = sidx[r], dd = didx[r];
            float4 p1 = ((const float4*)P1)[(size_t)s * DV4 + cg];
            float4 p2 = ((const float4*)P2)[(size_t)dd * DV4 + cg];
            x += p1.x + p2.x; y += p1.y + p2.y;
            z += p1.z + p2.z; w += p1.w + p2.w;
        }
        x = fmaxf(x, 0.f); y = fmaxf(y, 0.f);
        z = fmaxf(z, 0.f); w = fmaxf(w, 0.f);
    }
    ((float4*)C)[(size_t)r * DV4 + cg] = make_float4(x, y, z, w);
}

__global__ void __launch_bounds__(256) gemm_k(const float* __restrict__ A,
                                              const float* __restrict__ W,
                                              float* __restrict__ C, int M, int mode,
                                              const float* __restrict__ R,
                                              const float* __restrict__ P1,
                                              const float* __restrict__ P2,
                                              const int* __restrict__ sidx,
                                              const int* __restrict__ didx) {
    extern __shared__ float sm[];
    float* Ws = sm;              // 128*128
    float* As = sm + 16384;      // 128 x 68 (transposed A tile, pitch 68)
    int tid = threadIdx.x;
    int row0 = blockIdx.x * 64;

    const float4* W4 = (const float4*)W;
    float4* Ws4 = (float4*)Ws;
#pragma unroll
    for (int i = 0; i < 16; i++) Ws4[tid + i * 256] = W4[tid + i * 256];

#pragma unroll
    for (int i = 0; i < 8; i++) {
        int j = tid + i * 256;          // 0..2047
        int r = j >> 5, kc = j & 31;
        int gr = row0 + r;
        float4 a = (gr < M) ? ((const float4*)A)[(size_t)gr * DV4 + kc]
                            : make_float4(0.f, 0.f, 0.f, 0.f);
        int kk = kc * 4;
        As[(kk + 0) * 68 + r] = a.x;
        As[(kk + 1) * 68 + r] = a.y;
        As[(kk + 2) * 68 + r] = a.z;
        As[(kk + 3) * 68 + r] = a.w;
    }
    __syncthreads();

    int rg = tid >> 5, cg = tid & 31;
    int rb = rg * 8;                    // 8 consecutive rows -> 4 packed row-pairs
    unsigned long long acc[4][4];
#pragma unroll
    for (int i = 0; i < 4; i++)
#pragma unroll
        for (int j = 0; j < 4; j++) acc[i][j] = 0ull;

#pragma unroll 4
    for (int k = 0; k < 128; k++) {
        float4 wv = *(const float4*)&Ws[k * 128 + cg * 4];
        unsigned long long wp0 = pack2(wv.x), wp1 = pack2(wv.y);
        unsigned long long wp2 = pack2(wv.z), wp3 = pack2(wv.w);
        const ulonglong2* ap = (const ulonglong2*)&As[k * 68 + rb];
        ulonglong2 aA = ap[0], aB = ap[1];
        unsigned long long ar0 = aA.x, ar1 = aA.y, ar2 = aB.x, ar3 = aB.y;
        FMA2(acc[0][0], ar0, wp0); FMA2(acc[0][1], ar0, wp1);
        FMA2(acc[0][2], ar0, wp2); FMA2(acc[0][3], ar0, wp3);
        FMA2(acc[1][0], ar1, wp0); FMA2(acc[1][1], ar1, wp1);
        FMA2(acc[1][2], ar1, wp2); FMA2(acc[1][3], ar1, wp3);
        FMA2(acc[2][0], ar2, wp0); FMA2(acc[2][1], ar2, wp1);
        FMA2(acc[2][2], ar2, wp2); FMA2(acc[2][3], ar2, wp3);
        FMA2(acc[3][0], ar3, wp0); FMA2(acc[3][1], ar3, wp1);
        FMA2(acc[3][2], ar3, wp2); FMA2(acc[3][3], ar3, wp3);
    }

#pragma unroll
    for (int i = 0; i < 4; i++) {
        float lo[4], hi[4];
#pragma unroll
        for (int j = 0; j < 4; j++) {
            unsigned int l32, h32;
            asm("mov.b64 {%0,%1}, %2;" : "=r"(l32), "=r"(h32) : "l"(acc[i][j]));
            lo[j] = __uint_as_float(l32);
            hi[j] = __uint_as_float(h32);
        }
        int r = row0 + rb + 2 * i;
        emit_row(C, mode, R, P1, P2, sidx, didx, r,     cg, M, lo[0], lo[1], lo[2], lo[3]);
        emit_row(C, mode, R, P1, P2, sidx, didx, r + 1, cg, M, hi[0], hi[1], hi[2], hi[3]);
    }
}

// ---------------- attention kernels ----------------
__global__ void scores_k(const int* __restrict__ src, const int* __restrict__ dst, int E) {
    int gt = blockIdx.x * blockDim.x + threadIdx.x;
    int w = gt >> 5, l = gt & 31;
    if (w >= E) return;
    int s = src[w], d = dst[w];
    float4 q4 = ((const float4*)g_q)[(size_t)d * DV4 + l];
    float4 k4 = ((const float4*)g_k)[(size_t)s * DV4 + l];
    float4 e4 = ((const float4*)g_ek)[(size_t)w * DV4 + l];
    float p = q4.x * (k4.x + e4.x) + q4.y * (k4.y + e4.y)
            + q4.z * (k4.z + e4.z) + q4.w * (k4.w + e4.w);
    p += __shfl_down_sync(0xffffffffu, p, 4, 8);
    p += __shfl_down_sync(0xffffffffu, p, 2, 8);
    p += __shfl_down_sync(0xffffffffu, p, 1, 8);
    if ((l & 7) == 0) g_sc[(size_t)w * 4 + (l >> 3)] = p * 0.17677669529663689f;
}

__global__ void stats_k(int N) {   // online segment softmax stats per node/head
    int n = blockIdx.x * blockDim.x + threadIdx.x;
    if (n >= N) return;
    int b = g_rowptr[n], e = g_rowptr[n + 1];
    float m0 = -1e30f, m1 = -1e30f, m2 = -1e30f, m3 = -1e30f;
    float s0 = 0.f, s1 = 0.f, s2 = 0.f, s3 = 0.f;
    for (int j = b; j < e; j++) {
        int eid = g_eid[j];
        float4 sc = ((const float4*)g_sc)[eid];
        float nm;
        nm = fmaxf(m0, sc.x); s0 = s0 * expf(m0 - nm) + expf(sc.x - nm); m0 = nm;
        nm = fmaxf(m1, sc.y); s1 = s1 * expf(m1 - nm) + expf(sc.y - nm); m1 = nm;
        nm = fmaxf(m2, sc.z); s2 = s2 * expf(m2 - nm) + expf(sc.z - nm); m2 = nm;
        nm = fmaxf(m3, sc.w); s3 = s3 * expf(m3 - nm) + expf(sc.w - nm); m3 = nm;
    }
    g_m[n * 4 + 0] = m0; g_m[n * 4 + 1] = m1; g_m[n * 4 + 2] = m2; g_m[n * 4 + 3] = m3;
    g_den[n * 4 + 0] = s0; g_den[n * 4 + 1] = s1; g_den[n * 4 + 2] = s2; g_den[n * 4 + 3] = s3;
}

__global__ void agg_k(const int* __restrict__ src, int N) {  // warp per node
    int gt = blockIdx.x * blockDim.x + threadIdx.x;
    int n = gt >> 5, l = gt & 31;
    if (n >= N) return;
    int h = l >> 3;
    float m = g_m[n * 4 + h];
    float inv = 1.0f / (g_den[n * 4 + h] + 1e-16f);
    int b = g_rowptr[n], e = g_rowptr[n + 1];
    float4 acc = make_float4(0.f, 0.f, 0.f, 0.f);
    for (int j = b; j < e; j++) {
        int eid = g_eid[j];
        int s = src[eid];
        float a = expf(g_sc[(size_t)eid * 4 + h] - m) * inv;
        float4 v4 = ((const float4*)g_v)[(size_t)s * DV4 + l];
        float4 ev4 = ((const float4*)g_ev)[(size_t)eid * DV4 + l];
        acc.x += a * (v4.x + ev4.x);
        acc.y += a * (v4.y + ev4.y);
        acc.z += a * (v4.z + ev4.z);
        acc.w += a * (v4.w + ev4.w);
    }
    ((float4*)g_agg)[(size_t)n * DV4 + l] = acc;
}

// ---------------- readout ----------------
__global__ void zero_readout_k() {
    int i = blockIdx.x * blockDim.x + threadIdx.x;
    if (i < GMAX * DD) { g_gagg[i] = 0.f; g_eagg[i] = 0.f; }
    if (i < GMAX) { g_gcnt[i] = 0.f; g_ecnt[i] = 0.f; }
}

__global__ void node_scatter_k(const int* __restrict__ nt, const int* __restrict__ batch, int n32) {
    int i = blockIdx.x * blockDim.x + threadIdx.x;
    if (i >= n32) return;
    int n = i >> 5, c = i & 31;
    if (nt[n] != 0) return;
    int g = batch[n];
    float4 f = ((const float4*)g_feat)[i];
    atomicAdd(&g_gagg[g * DD + c * 4 + 0], f.x);
    atomicAdd(&g_gagg[g * DD + c * 4 + 1], f.y);
    atomicAdd(&g_gagg[g * DD + c * 4 + 2], f.z);
    atomicAdd(&g_gagg[g * DD + c * 4 + 3], f.w);
    if (c == 0) atomicAdd(&g_gcnt[g], 1.0f);
}

__global__ void edge_scatter_k(const int* __restrict__ src, const int* __restrict__ batch, int e32) {
    int i = blockIdx.x * blockDim.x + threadIdx.x;
    if (i >= e32) return;
    int ed = i >> 5, c = i & 31;
    int g = batch[src[ed]];
    float4 f = ((const float4*)g_e)[i];
    atomicAdd(&g_eagg[g * DD + c * 4 + 0], f.x);
    atomicAdd(&g_eagg[g * DD + c * 4 + 1], f.y);
    atomicAdd(&g_eagg[g * DD + c * 4 + 2], f.z);
    atomicAdd(&g_eagg[g * DD + c * 4 + 3], f.w);
    if (c == 0) atomicAdd(&g_ecnt[g], 1.0f);
}

__global__ void final_k(const float* __restrict__ QW1, const float* __restrict__ Qb1,
                        const float* __restrict__ QW2, const float* __restrict__ Qb2,
                        float* __restrict__ out, int A) {
    int g = blockIdx.x;
    int t = threadIdx.x;
    __shared__ float ga[256];
    __shared__ float hh[128];
    __shared__ float lg[128];
    __shared__ float lse_s;
    float ncnt = fmaxf(g_gcnt[g], 1.0f);
    float ecnt = fmaxf(g_ecnt[g], 1.0f);
    if (t < 128) ga[t] = g_gagg[g * DD + t] / ncnt;
    else         ga[t] = g_eagg[g * DD + (t - 128)] / ecnt;
    __syncthreads();
    if (t < 128) {
        float acc = Qb1[t];
        for (int j = 0; j < 256; j++) acc += ga[j] * QW1[j * 128 + t];
        hh[t] = fmaxf(acc, 0.f);
    }
    __syncthreads();
    if (t < A) {
        float acc = Qb2[t];
        for (int j = 0; j < 128; j++) acc += hh[j] * QW2[j * A + t];
        lg[t] = acc;
    }
    __syncthreads();
    if (t == 0) {
        float m = -1e30f;
        for (int i = 0; i < A; i++) m = fmaxf(m, lg[i]);
        float s = 0.f;
        for (int i = 0; i < A; i++) s += expf(lg[i] - m);
        lse_s = logf(s) + m;
    }
    __syncthreads();
    if (t < A) out[g * A + t] = lg[t] - lse_s;
}

// ---------------- host launcher ----------------
extern "C" void kernel_launch(void* const* d_in, const int* in_sizes, int n_in,
                              void* d_out, int out_size) {
    const int*   x         = (const int*)d_in[0];
    const int*   node_type = (const int*)d_in[1];
    const int*   batch     = (const int*)d_in[2];
    const int*   eix       = (const int*)d_in[3];
    const int*   flow      = (const int*)d_in[4];
    const int*   pos       = (const int*)d_in[5];
    const int*   blk       = (const int*)d_in[6];
    const float* emb       = (const float*)d_in[8];
    const float* fe        = (const float*)d_in[9];
    const float* pe        = (const float*)d_in[10];
    const float* be        = (const float*)d_in[11];
    const float* Wq        = (const float*)d_in[12];
    const float* Wk        = (const float*)d_in[13];
    const float* Wv        = (const float*)d_in[14];
    const float* Wek       = (const float*)d_in[15];
    const float* Wev       = (const float*)d_in[16];
    const float* Wo        = (const float*)d_in[17];
    const float* Weu       = (const float*)d_in[18];
    const float* QW1       = (const float*)d_in[19];
    const float* Qb1       = (const float*)d_in[20];
    const float* QW2       = (const float*)d_in[21];
    const float* Qb2       = (const float*)d_in[22];

    int N = in_sizes[0];
    int E = in_sizes[4];
    int L = in_sizes[12] / (128 * 128);
    int A = in_sizes[22];
    const int* src = eix;
    const int* dst = eix + E;

    float *p_feat, *p_q, *p_k, *p_v, *p_agg, *p_P1, *p_P2, *p_e, *p_ek, *p_ev;
    cudaGetSymbolAddress((void**)&p_feat, g_feat);
    cudaGetSymbolAddress((void**)&p_q, g_q);
    cudaGetSymbolAddress((void**)&p_k, g_k);
    cudaGetSymbolAddress((void**)&p_v, g_v);
    cudaGetSymbolAddress((void**)&p_agg, g_agg);
    cudaGetSymbolAddress((void**)&p_P1, g_P1);
    cudaGetSymbolAddress((void**)&p_P2, g_P2);
    cudaGetSymbolAddress((void**)&p_e, g_e);
    cudaGetSymbolAddress((void**)&p_ek, g_ek);
    cudaGetSymbolAddress((void**)&p_ev, g_ev);

    cudaFuncSetAttribute(gemm_k, cudaFuncAttributeMaxDynamicSharedMemorySize, SMEM_GEMM);

    const int T = 256;
    // CSR build (dst-grouped), once per call
    zero_cnt_k<<<ceil_div(N, T), T>>>(N);
    hist_k<<<ceil_div(E, T), T>>>(dst, E);
    scan_k<<<1, 1024>>>(N);
    zero_cnt_k<<<ceil_div(N, T), T>>>(N);
    fill_k<<<ceil_div(E, T), T>>>(dst, E);
    // input encodings
    embed_k<<<ceil_div(N * 32, T), T>>>(x, emb, N * 32);
    edge_enc_k<<<ceil_div(E * 32, T), T>>>(flow, pos, blk, src, dst, fe, pe, be, E * 32);

    int gN = ceil_div(N, 64), gE = ceil_div(E, 64);
    for (int l = 0; l < L; l++) {
        const float* wq = Wq + (size_t)l * 16384;
        const float* wk = Wk + (size_t)l * 16384;
        const float* wv = Wv + (size_t)l * 16384;
        const float* wek = Wek + (size_t)l * 16384;
        const float* wev = Wev + (size_t)l * 16384;
        const float* wo = Wo + (size_t)l * 16384;
        const float* weu = Weu + (size_t)l * 49152;

        gemm_k<<<gN, T, SMEM_GEMM>>>(p_feat, wq, p_q, N, 0, 0, 0, 0, 0, 0);
        gemm_k<<<gN, T, SMEM_GEMM>>>(p_feat, wk, p_k, N, 0, 0, 0, 0, 0, 0);
        gemm_k<<<gN, T, SMEM_GEMM>>>(p_feat, wv, p_v, N, 0, 0, 0, 0, 0, 0);
        gemm_k<<<gE, T, SMEM_GEMM>>>(p_e, wek, p_ek, E, 0, 0, 0, 0, 0, 0);
        gemm_k<<<gE, T, SMEM_GEMM>>>(p_e, wev, p_ev, E, 0, 0, 0, 0, 0, 0);

        scores_k<<<ceil_div(E * 32, T), T>>>(src, dst, E);
        stats_k<<<ceil_div(N, T), T>>>(N);
        agg_k<<<ceil_div(N * 32, T), T>>>(src, N);

        // factored edge update: P1 = feat@Weu[0:128], P2 = feat@Weu[128:256]
        gemm_k<<<gN, T, SMEM_GEMM>>>(p_feat, weu, p_P1, N, 0, 0, 0, 0, 0, 0);
        gemm_k<<<gN, T, SMEM_GEMM>>>(p_feat, weu + 16384, p_P2, N, 0, 0, 0, 0, 0, 0);
        // e = relu(e + e@Weu[256:384] + P1[src] + P2[dst])   (in-place, row-local)
        gemm_k<<<gE, T, SMEM_GEMM>>>(p_e, weu + 32768, p_e, E, 2, p_e, p_P1, p_P2, src, dst);
        // feat = relu(feat + agg@Wo)   (in-place residual)
        gemm_k<<<gN, T, SMEM_GEMM>>>(p_agg, wo, p_feat, N, 1, p_feat, 0, 0, 0, 0);
    }

    // readout
    zero_readout_k<<<ceil_div(GMAX * DD, T), T>>>();
    node_scatter_k<<<ceil_div(N * 32, T), T>>>(node_type, batch, N * 32);
    edge_scatter_k<<<ceil_div(E * 32, T), T>>>(src, batch, E * 32);
    final_k<<<GMAX, T>>>(QW1, Qb1, QW2, Qb2, (float*)d_out, A);
}

// round 8
// speedup vs baseline: 1.1985x; 1.1985x over previous
#include <cuda_runtime.h>
#include <math.h>

#define DD   128
#define DV4  32
#define NH   4
#define GMAX 64
#define NMAX 100000
#define EMAX 500000
#define P_AS 132
#define SMEM_G ((128*P_AS + 128*128)*4)   // 133,120 B: As tile + W tile

// ---------------- device scratch (static, no allocation) ----------------
__device__ float g_feat[NMAX*DD];
__device__ float g_q[NMAX*DD];
__device__ float g_k[NMAX*DD];
__device__ float g_v[NMAX*DD];
__device__ float g_agg[NMAX*DD];
__device__ float g_P1[NMAX*DD];
__device__ float g_P2[NMAX*DD];
__device__ float g_e[EMAX*DD];
__device__ float g_ev[EMAX*DD];
__device__ float g_sc[EMAX*NH];
__device__ float g_m[NMAX*NH];
__device__ float g_den[NMAX*NH];
__device__ int   g_cnt[NMAX];
__device__ int   g_rowptr[NMAX+1];
__device__ int   g_eid[EMAX];
__device__ float g_gagg[GMAX*DD];
__device__ float g_eagg[GMAX*DD];
__device__ float g_gcnt[GMAX];
__device__ float g_ecnt[GMAX];

static inline int ceil_div(int a, int b) { return (a + b - 1) / b; }

__device__ __forceinline__ unsigned long long pack2(float x) {
    unsigned long long r;
    asm("mov.b64 %0, {%1, %1};" : "=l"(r) : "f"(x));
    return r;
}
#define FMA2(d, a, b) asm("fma.rn.f32x2 %0, %1, %2, %0;" : "+l"(d) : "l"(a), "l"(b))

// ---------------- setup kernels ----------------
__global__ void zero_cnt_k(int N) {
    int i = blockIdx.x * blockDim.x + threadIdx.x;
    if (i < N) g_cnt[i] = 0;
}

__global__ void hist_k(const int* __restrict__ dst, int E) {
    int i = blockIdx.x * blockDim.x + threadIdx.x;
    if (i < E) atomicAdd(&g_cnt[dst[i]], 1);
}

__global__ void scan_k(int N) {
    __shared__ int sh[1024];
    __shared__ int carry_s;
    int t = threadIdx.x;
    if (t == 0) carry_s = 0;
    __syncthreads();
    for (int base = 0; base < N; base += 1024) {
        int v = (base + t < N) ? g_cnt[base + t] : 0;
        sh[t] = v;
        __syncthreads();
        for (int off = 1; off < 1024; off <<= 1) {
            int tmp = (t >= off) ? sh[t - off] : 0;
            __syncthreads();
            sh[t] += tmp;
            __syncthreads();
        }
        if (base + t < N) g_rowptr[base + t] = carry_s + sh[t] - v;
        __syncthreads();
        if (t == 0) carry_s += sh[1023];
        __syncthreads();
    }
    if (t == 0) g_rowptr[N] = carry_s;
}

__global__ void fill_k(const int* __restrict__ dst, int E) {
    int i = blockIdx.x * blockDim.x + threadIdx.x;
    if (i >= E) return;
    int d = dst[i];
    int slot = atomicAdd(&g_cnt[d], 1);
    g_eid[g_rowptr[d] + slot] = i;
}

__global__ void embed_k(const int* __restrict__ x, const float* __restrict__ emb, int n32) {
    int i = blockIdx.x * blockDim.x + threadIdx.x;
    if (i >= n32) return;
    int n = i >> 5, c = i & 31;
    ((float4*)g_feat)[i] = ((const float4*)emb)[(size_t)x[n] * DV4 + c];
}

__global__ void edge_enc_k(const int* __restrict__ flow, const int* __restrict__ pos,
                           const int* __restrict__ blk, const int* __restrict__ src,
                           const int* __restrict__ dst,
                           const float* __restrict__ fe, const float* __restrict__ pe,
                           const float* __restrict__ be, int e32) {
    int i = blockIdx.x * blockDim.x + threadIdx.x;
    if (i >= e32) return;
    int ed = i >> 5, c = i & 31;
    int cr = (blk[src[ed]] != blk[dst[ed]]) ? 1 : 0;
    float4 a = ((const float4*)fe)[flow[ed] * DV4 + c];
    float4 b = ((const float4*)pe)[pos[ed] * DV4 + c];
    float4 d = ((const float4*)be)[cr * DV4 + c];
    float4 o;
    o.x = a.x + b.x + d.x; o.y = a.y + b.y + d.y;
    o.z = a.z + b.z + d.z; o.w = a.w + b.w + d.w;
    ((float4*)g_e)[i] = o;
}

// ---------------- shared GEMM building blocks (512 thr, 128-row tile) ----------
__device__ __forceinline__ void stage_A(const float* __restrict__ A, float* As,
                                        int row0, int M, int tid) {
    int lane = tid & 31;
#pragma unroll
    for (int it = 0; it < 8; it++) {
        int j = tid + it * 512;
        int r = j >> 5, kc = j & 31;
        int gr = row0 + r;
        float4 av = (gr < M) ? ((const float4*)A)[(size_t)gr * DV4 + kc]
                             : make_float4(0.f, 0.f, 0.f, 0.f);
        float vals[4] = {av.x, av.y, av.z, av.w};
#pragma unroll
        for (int q = 0; q < 4; q++) {
            int i = ((lane >> 3) + q) & 3;   // diagonal order: 4-way instead of 16-way
            As[(kc * 4 + i) * P_AS + r] = vals[i];
        }
    }
}

__device__ __forceinline__ void load_W(const float* __restrict__ W, float* Ws, int tid) {
#pragma unroll
    for (int it = 0; it < 8; it++)
        ((float4*)Ws)[tid + it * 512] = ((const float4*)W)[tid + it * 512];
}

__device__ __forceinline__ void mainloop(const float* As, const float* Ws,
                                         int rb, int cg, unsigned long long acc[4][4]) {
#pragma unroll
    for (int i = 0; i < 4; i++)
#pragma unroll
        for (int j = 0; j < 4; j++) acc[i][j] = 0ull;
#pragma unroll 4
    for (int k = 0; k < 128; k++) {
        float4 wv = *(const float4*)&Ws[k * 128 + cg * 4];
        unsigned long long wp0 = pack2(wv.x), wp1 = pack2(wv.y);
        unsigned long long wp2 = pack2(wv.z), wp3 = pack2(wv.w);
        const ulonglong2* ap = (const ulonglong2*)&As[k * P_AS + rb];
        ulonglong2 aA = ap[0], aB = ap[1];
        unsigned long long ar0 = aA.x, ar1 = aA.y, ar2 = aB.x, ar3 = aB.y;
        FMA2(acc[0][0], ar0, wp0); FMA2(acc[0][1], ar0, wp1);
        FMA2(acc[0][2], ar0, wp2); FMA2(acc[0][3], ar0, wp3);
        FMA2(acc[1][0], ar1, wp0); FMA2(acc[1][1], ar1, wp1);
        FMA2(acc[1][2], ar1, wp2); FMA2(acc[1][3], ar1, wp3);
        FMA2(acc[2][0], ar2, wp0); FMA2(acc[2][1], ar2, wp1);
        FMA2(acc[2][2], ar2, wp2); FMA2(acc[2][3], ar2, wp3);
        FMA2(acc[3][0], ar3, wp0); FMA2(acc[3][1], ar3, wp1);
        FMA2(acc[3][2], ar3, wp2); FMA2(acc[3][3], ar3, wp3);
    }
}

__device__ __forceinline__ void unpack_acc(unsigned long long acc[4][4],
                                           float lo[4][4], float hi[4][4]) {
#pragma unroll
    for (int i = 0; i < 4; i++)
#pragma unroll
        for (int j = 0; j < 4; j++) {
            unsigned int l32, h32;
            asm("mov.b64 {%0,%1}, %2;" : "=r"(l32), "=r"(h32) : "l"(acc[i][j]));
            lo[i][j] = __uint_as_float(l32);
            hi[i][j] = __uint_as_float(h32);
        }
}

__device__ __forceinline__ void write_plain(float* __restrict__ C, int row0, int rb, int cg,
                                            int M, float lo[4][4], float hi[4][4]) {
#pragma unroll
    for (int i = 0; i < 4; i++) {
        int r = row0 + rb + 2 * i;
        if (r < M)
            ((float4*)C)[(size_t)r * DV4 + cg] = make_float4(lo[i][0], lo[i][1], lo[i][2], lo[i][3]);
        if (r + 1 < M)
            ((float4*)C)[(size_t)(r + 1) * DV4 + cg] = make_float4(hi[i][0], hi[i][1], hi[i][2], hi[i][3]);
    }
}

// ---------------- fused node GEMM: q,k,v,P1,P2 from feat (5 passes) -----------
__global__ void __launch_bounds__(512) gemm_node5_k(
        const float* __restrict__ A,
        const float* __restrict__ W0, const float* __restrict__ W1,
        const float* __restrict__ W2, const float* __restrict__ W3,
        const float* __restrict__ W4,
        float* __restrict__ C0, float* __restrict__ C1, float* __restrict__ C2,
        float* __restrict__ C3, float* __restrict__ C4, int M) {
    extern __shared__ float sm[];
    float* As = sm;                 // 128 x P_AS
    float* Ws = sm + 128 * P_AS;    // 128 x 128
    int tid = threadIdx.x;
    int row0 = blockIdx.x * 128;
    int rb = (tid >> 5) * 8, cg = tid & 31;

    stage_A(A, As, row0, M, tid);
    const float* Wp[5] = {W0, W1, W2, W3, W4};
    float* Cp[5] = {C0, C1, C2, C3, C4};
    unsigned long long acc[4][4];
    float lo[4][4], hi[4][4];
#pragma unroll
    for (int p = 0; p < 5; p++) {
        __syncthreads();
        load_W(Wp[p], Ws, tid);
        __syncthreads();
        mainloop(As, Ws, rb, cg, acc);
        unpack_acc(acc, lo, hi);
        write_plain(Cp[p], row0, rb, cg, M, lo, hi);
    }
}

// ------- fused edge GEMM: pass0 Wek -> scores (ek never stored), pass1 Wev -> ev
__global__ void __launch_bounds__(512) gemm_edge2_k(
        const float* __restrict__ A, const float* __restrict__ Wek,
        const float* __restrict__ Wev, float* __restrict__ Cev,
        const int* __restrict__ src, const int* __restrict__ dst, int M) {
    extern __shared__ float sm[];
    float* As = sm;
    float* Ws = sm + 128 * P_AS;
    int tid = threadIdx.x;
    int row0 = blockIdx.x * 128;
    int rb = (tid >> 5) * 8, cg = tid & 31;

    stage_A(A, As, row0, M, tid);
    unsigned long long acc[4][4];
    float lo[4][4], hi[4][4];

    // pass 0: ek in registers -> per-edge attention scores
    __syncthreads();
    load_W(Wek, Ws, tid);
    __syncthreads();
    mainloop(As, Ws, rb, cg, acc);
    unpack_acc(acc, lo, hi);
#pragma unroll
    for (int ri = 0; ri < 8; ri++) {
        int er = row0 + rb + ri;
        if (er < M) {
            int i = ri >> 1;
            float e0 = (ri & 1) ? hi[i][0] : lo[i][0];
            float e1 = (ri & 1) ? hi[i][1] : lo[i][1];
            float e2 = (ri & 1) ? hi[i][2] : lo[i][2];
            float e3 = (ri & 1) ? hi[i][3] : lo[i][3];
            int s = src[er], d = dst[er];
            float4 qv = ((const float4*)g_q)[(size_t)d * DV4 + cg];
            float4 kv = ((const float4*)g_k)[(size_t)s * DV4 + cg];
            float p = qv.x * (kv.x + e0) + qv.y * (kv.y + e1)
                    + qv.z * (kv.z + e2) + qv.w * (kv.w + e3);
            p += __shfl_down_sync(0xffffffffu, p, 4, 8);
            p += __shfl_down_sync(0xffffffffu, p, 2, 8);
            p += __shfl_down_sync(0xffffffffu, p, 1, 8);
            if ((cg & 7) == 0)
                g_sc[(size_t)er * 4 + (cg >> 3)] = p * 0.17677669529663689f;
        }
    }

    // pass 1: ev materialized
    __syncthreads();
    load_W(Wev, Ws, tid);
    __syncthreads();
    mainloop(As, Ws, rb, cg, acc);
    unpack_acc(acc, lo, hi);
    write_plain(Cev, row0, rb, cg, M, lo, hi);
}

// ------- single-pass GEMM with residual epilogue -------------------------------
// mode 1: C = relu(R + A@W);  mode 2: C = relu(R + A@W + P1[sidx]+P2[didx])
__global__ void __launch_bounds__(512) gemm_epi_k(
        const float* __restrict__ A, const float* __restrict__ W,
        float* __restrict__ C, const float* __restrict__ R,
        const float* __restrict__ P1, const float* __restrict__ P2,
        const int* __restrict__ sidx, const int* __restrict__ didx,
        int M, int mode) {
    extern __shared__ float sm[];
    float* As = sm;
    float* Ws = sm + 128 * P_AS;
    int tid = threadIdx.x;
    int row0 = blockIdx.x * 128;
    int rb = (tid >> 5) * 8, cg = tid & 31;

    stage_A(A, As, row0, M, tid);
    __syncthreads();
    load_W(W, Ws, tid);
    __syncthreads();
    unsigned long long acc[4][4];
    mainloop(As, Ws, rb, cg, acc);
    float lo[4][4], hi[4][4];
    unpack_acc(acc, lo, hi);
#pragma unroll
    for (int ri = 0; ri < 8; ri++) {
        int r = row0 + rb + ri;
        if (r >= M) continue;
        int i = ri >> 1;
        float x = (ri & 1) ? hi[i][0] : lo[i][0];
        float y = (ri & 1) ? hi[i][1] : lo[i][1];
        float z = (ri & 1) ? hi[i][2] : lo[i][2];
        float w = (ri & 1) ? hi[i][3] : lo[i][3];
        float4 res = ((const float4*)R)[(size_t)r * DV4 + cg];
        x += res.x; y += res.y; z += res.z; w += res.w;
        if (mode == 2) {
            int s = sidx[r], dd = didx[r];
            float4 p1 = ((const float4*)P1)[(size_t)s * DV4 + cg];
            float4 p2 = ((const float4*)P2)[(size_t)dd * DV4 + cg];
            x += p1.x + p2.x; y += p1.y + p2.y;
            z += p1.z + p2.z; w += p1.w + p2.w;
        }
        x = fmaxf(x, 0.f); y = fmaxf(y, 0.f);
        z = fmaxf(z, 0.f); w = fmaxf(w, 0.f);
        ((float4*)C)[(size_t)r * DV4 + cg] = make_float4(x, y, z, w);
    }
}

// ---------------- attention kernels ----------------
__global__ void stats_k(int N) {
    int n = blockIdx.x * blockDim.x + threadIdx.x;
    if (n >= N) return;
    int b = g_rowptr[n], e = g_rowptr[n + 1];
    float m0 = -1e30f, m1 = -1e30f, m2 = -1e30f, m3 = -1e30f;
    float s0 = 0.f, s1 = 0.f, s2 = 0.f, s3 = 0.f;
    for (int j = b; j < e; j++) {
        int eid = g_eid[j];
        float4 sc = ((const float4*)g_sc)[eid];
        float nm;
        nm = fmaxf(m0, sc.x); s0 = s0 * expf(m0 - nm) + expf(sc.x - nm); m0 = nm;
        nm = fmaxf(m1, sc.y); s1 = s1 * expf(m1 - nm) + expf(sc.y - nm); m1 = nm;
        nm = fmaxf(m2, sc.z); s2 = s2 * expf(m2 - nm) + expf(sc.z - nm); m2 = nm;
        nm = fmaxf(m3, sc.w); s3 = s3 * expf(m3 - nm) + expf(sc.w - nm); m3 = nm;
    }
    g_m[n * 4 + 0] = m0; g_m[n * 4 + 1] = m1; g_m[n * 4 + 2] = m2; g_m[n * 4 + 3] = m3;
    g_den[n * 4 + 0] = s0; g_den[n * 4 + 1] = s1; g_den[n * 4 + 2] = s2; g_den[n * 4 + 3] = s3;
}

__global__ void agg_k(const int* __restrict__ src, int N) {   // warp per node
    int gt = blockIdx.x * blockDim.x + threadIdx.x;
    int n = gt >> 5, l = gt & 31;
    if (n >= N) return;
    int h = l >> 3;
    float m = g_m[n * 4 + h];
    float inv = 1.0f / (g_den[n * 4 + h] + 1e-16f);
    int b = g_rowptr[n], e = g_rowptr[n + 1];
    float4 acc = make_float4(0.f, 0.f, 0.f, 0.f);
    for (int j = b; j < e; j++) {
        int eid = g_eid[j];
        int s = src[eid];
        float a = expf(g_sc[(size_t)eid * 4 + h] - m) * inv;
        float4 v4 = ((const float4*)g_v)[(size_t)s * DV4 + l];
        float4 ev4 = ((const float4*)g_ev)[(size_t)eid * DV4 + l];
        acc.x += a * (v4.x + ev4.x);
        acc.y += a * (v4.y + ev4.y);
        acc.z += a * (v4.z + ev4.z);
        acc.w += a * (v4.w + ev4.w);
    }
    ((float4*)g_agg)[(size_t)n * DV4 + l] = acc;
}

// ---------------- readout ----------------
__global__ void zero_readout_k() {
    int i = blockIdx.x * blockDim.x + threadIdx.x;
    if (i < GMAX * DD) { g_gagg[i] = 0.f; g_eagg[i] = 0.f; }
    if (i < GMAX) { g_gcnt[i] = 0.f; g_ecnt[i] = 0.f; }
}

__global__ void node_scatter_k(const int* __restrict__ nt, const int* __restrict__ batch, int n32) {
    int i = blockIdx.x * blockDim.x + threadIdx.x;
    if (i >= n32) return;
    int n = i >> 5, c = i & 31;
    if (nt[n] != 0) return;
    int g = batch[n];
    float4 f = ((const float4*)g_feat)[i];
    atomicAdd(&g_gagg[g * DD + c * 4 + 0], f.x);
    atomicAdd(&g_gagg[g * DD + c * 4 + 1], f.y);
    atomicAdd(&g_gagg[g * DD + c * 4 + 2], f.z);
    atomicAdd(&g_gagg[g * DD + c * 4 + 3], f.w);
    if (c == 0) atomicAdd(&g_gcnt[g], 1.0f);
}

__global__ void edge_scatter_k(const int* __restrict__ src, const int* __restrict__ batch, int e32) {
    int i = blockIdx.x * blockDim.x + threadIdx.x;
    if (i >= e32) return;
    int ed = i >> 5, c = i & 31;
    int g = batch[src[ed]];
    float4 f = ((const float4*)g_e)[i];
    atomicAdd(&g_eagg[g * DD + c * 4 + 0], f.x);
    atomicAdd(&g_eagg[g * DD + c * 4 + 1], f.y);
    atomicAdd(&g_eagg[g * DD + c * 4 + 2], f.z);
    atomicAdd(&g_eagg[g * DD + c * 4 + 3], f.w);
    if (c == 0) atomicAdd(&g_ecnt[g], 1.0f);
}

__global__ void final_k(const float* __restrict__ QW1, const float* __restrict__ Qb1,
                        const float* __restrict__ QW2, const float* __restrict__ Qb2,
                        float* __restrict__ out, int A) {
    int g = blockIdx.x;
    int t = threadIdx.x;
    __shared__ float ga[256];
    __shared__ float hh[128];
    __shared__ float lg[128];
    __shared__ float lse_s;
    float ncnt = fmaxf(g_gcnt[g], 1.0f);
    float ecnt = fmaxf(g_ecnt[g], 1.0f);
    if (t < 128) ga[t] = g_gagg[g * DD + t] / ncnt;
    else         ga[t] = g_eagg[g * DD + (t - 128)] / ecnt;
    __syncthreads();
    if (t < 128) {
        float acc = Qb1[t];
        for (int j = 0; j < 256; j++) acc += ga[j] * QW1[j * 128 + t];
        hh[t] = fmaxf(acc, 0.f);
    }
    __syncthreads();
    if (t < A) {
        float acc = Qb2[t];
        for (int j = 0; j < 128; j++) acc += hh[j] * QW2[j * A + t];
        lg[t] = acc;
    }
    __syncthreads();
    if (t == 0) {
        float m = -1e30f;
        for (int i = 0; i < A; i++) m = fmaxf(m, lg[i]);
        float s = 0.f;
        for (int i = 0; i < A; i++) s += expf(lg[i] - m);
        lse_s = logf(s) + m;
    }
    __syncthreads();
    if (t < A) out[g * A + t] = lg[t] - lse_s;
}

// ---------------- host launcher ----------------
extern "C" void kernel_launch(void* const* d_in, const int* in_sizes, int n_in,
                              void* d_out, int out_size) {
    const int*   x         = (const int*)d_in[0];
    const int*   node_type = (const int*)d_in[1];
    const int*   batch     = (const int*)d_in[2];
    const int*   eix       = (const int*)d_in[3];
    const int*   flow      = (const int*)d_in[4];
    const int*   pos       = (const int*)d_in[5];
    const int*   blk       = (const int*)d_in[6];
    const float* emb       = (const float*)d_in[8];
    const float* fe        = (const float*)d_in[9];
    const float* pe        = (const float*)d_in[10];
    const float* be        = (const float*)d_in[11];
    const float* Wq        = (const float*)d_in[12];
    const float* Wk        = (const float*)d_in[13];
    const float* Wv        = (const float*)d_in[14];
    const float* Wek       = (const float*)d_in[15];
    const float* Wev       = (const float*)d_in[16];
    const float* Wo        = (const float*)d_in[17];
    const float* Weu       = (const float*)d_in[18];
    const float* QW1       = (const float*)d_in[19];
    const float* Qb1       = (const float*)d_in[20];
    const float* QW2       = (const float*)d_in[21];
    const float* Qb2       = (const float*)d_in[22];

    int N = in_sizes[0];
    int E = in_sizes[4];
    int L = in_sizes[12] / (128 * 128);
    int A = in_sizes[22];
    const int* src = eix;
    const int* dst = eix + E;

    float *p_feat, *p_q, *p_k, *p_v, *p_agg, *p_P1, *p_P2, *p_e, *p_ev;
    cudaGetSymbolAddress((void**)&p_feat, g_feat);
    cudaGetSymbolAddress((void**)&p_q, g_q);
    cudaGetSymbolAddress((void**)&p_k, g_k);
    cudaGetSymbolAddress((void**)&p_v, g_v);
    cudaGetSymbolAddress((void**)&p_agg, g_agg);
    cudaGetSymbolAddress((void**)&p_P1, g_P1);
    cudaGetSymbolAddress((void**)&p_P2, g_P2);
    cudaGetSymbolAddress((void**)&p_e, g_e);
    cudaGetSymbolAddress((void**)&p_ev, g_ev);

    cudaFuncSetAttribute(gemm_node5_k, cudaFuncAttributeMaxDynamicSharedMemorySize, SMEM_G);
    cudaFuncSetAttribute(gemm_edge2_k, cudaFuncAttributeMaxDynamicSharedMemorySize, SMEM_G);
    cudaFuncSetAttribute(gemm_epi_k,   cudaFuncAttributeMaxDynamicSharedMemorySize, SMEM_G);

    const int T = 256;
    // CSR build (dst-grouped), once per call
    zero_cnt_k<<<ceil_div(N, T), T>>>(N);
    hist_k<<<ceil_div(E, T), T>>>(dst, E);
    scan_k<<<1, 1024>>>(N);
    zero_cnt_k<<<ceil_div(N, T), T>>>(N);
    fill_k<<<ceil_div(E, T), T>>>(dst, E);
    // input encodings
    embed_k<<<ceil_div(N * 32, T), T>>>(x, emb, N * 32);
    edge_enc_k<<<ceil_div(E * 32, T), T>>>(flow, pos, blk, src, dst, fe, pe, be, E * 32);

    int gN = ceil_div(N, 128), gE = ceil_div(E, 128);
    for (int l = 0; l < L; l++) {
        const float* wq  = Wq  + (size_t)l * 16384;
        const float* wk  = Wk  + (size_t)l * 16384;
        const float* wv  = Wv  + (size_t)l * 16384;
        const float* wek = Wek + (size_t)l * 16384;
        const float* wev = Wev + (size_t)l * 16384;
        const float* wo  = Wo  + (size_t)l * 16384;
        const float* weu = Weu + (size_t)l * 49152;

        // q,k,v,P1,P2 from feat in ONE staged pass set
        gemm_node5_k<<<gN, 512, SMEM_G>>>(p_feat, wq, wk, wv, weu, weu + 16384,
                                          p_q, p_k, p_v, p_P1, p_P2, N);
        // scores (ek fused away) + ev from e
        gemm_edge2_k<<<gE, 512, SMEM_G>>>(p_e, wek, wev, p_ev, src, dst, E);

        stats_k<<<ceil_div(N, T), T>>>(N);
        agg_k<<<ceil_div(N * 32, T), T>>>(src, N);

        // e = relu(e + e@Weu[256:384] + P1[src] + P2[dst])   (in-place, row-local)
        gemm_epi_k<<<gE, 512, SMEM_G>>>(p_e, weu + 32768, p_e, p_e, p_P1, p_P2, src, dst, E, 2);
        // feat = relu(feat + agg@Wo)
        gemm_epi_k<<<gN, 512, SMEM_G>>>(p_agg, wo, p_feat, p_feat, 0, 0, 0, 0, N, 1);
    }

    // readout
    zero_readout_k<<<ceil_div(GMAX * DD, T), T>>>();
    node_scatter_k<<<ceil_div(N * 32, T), T>>>(node_type, batch, N * 32);
    edge_scatter_k<<<ceil_div(E * 32, T), T>>>(src, batch, E * 32);
    final_k<<<GMAX, T>>>(QW1, Qb1, QW2, Qb2, (float*)d_out, A);
}

// round 9
// speedup vs baseline: 1.2082x; 1.0081x over previous
#include <cuda_runtime.h>
#include <math.h>

#define DD   128
#define DV4  32
#define NH   4
#define GMAX 64
#define NMAX 100000
#define EMAX 500000
#define P_AS 132
#define WS_FLOATS 16384
// double-buffered kernels: As + 2 W buffers
#define SMEM_DB ((128*P_AS + 2*WS_FLOATS)*4)   // 198,656 B
#define SMEM_SB ((128*P_AS + 1*WS_FLOATS)*4)   // 133,120 B

// ---------------- device scratch (static, no allocation) ----------------
__device__ float g_feat[NMAX*DD];
__device__ float g_q[NMAX*DD];
__device__ float g_k[NMAX*DD];
__device__ float g_v[NMAX*DD];
__device__ float g_agg[NMAX*DD];
__device__ float g_P1[NMAX*DD];
__device__ float g_P2[NMAX*DD];
__device__ float g_e[EMAX*DD];
__device__ float g_ev[EMAX*DD];
__device__ float g_sc[EMAX*NH];
__device__ float g_m[NMAX*NH];
__device__ float g_den[NMAX*NH];
__device__ int   g_cnt[NMAX];
__device__ int   g_rowptr[NMAX+1];
__device__ int   g_eid[EMAX];
__device__ float g_gagg[GMAX*DD];
__device__ float g_eagg[GMAX*DD];
__device__ float g_gcnt[GMAX];
__device__ float g_ecnt[GMAX];

static inline int ceil_div(int a, int b) { return (a + b - 1) / b; }

__device__ __forceinline__ unsigned long long pack2(float x) {
    unsigned long long r;
    asm("mov.b64 %0, {%1, %1};" : "=l"(r) : "f"(x));
    return r;
}
#define FMA2(d, a, b) asm("fma.rn.f32x2 %0, %1, %2, %0;" : "+l"(d) : "l"(a), "l"(b))

__device__ __forceinline__ void cp16(unsigned int dst, const void* src) {
    asm volatile("cp.async.cg.shared.global [%0], [%1], 16;" :: "r"(dst), "l"(src));
}
#define CP_COMMIT() asm volatile("cp.async.commit_group;")
#define CP_WAIT0()  asm volatile("cp.async.wait_group 0;")

// ---------------- setup kernels ----------------
__global__ void hist_k(const int* __restrict__ dst, int E) {
    int i = blockIdx.x * blockDim.x + threadIdx.x;
    if (i < E) atomicAdd(&g_cnt[dst[i]], 1);
}

__global__ void scan_k(int N) {
    __shared__ int sh[1024];
    __shared__ int carry_s;
    int t = threadIdx.x;
    if (t == 0) carry_s = 0;
    __syncthreads();
    for (int base = 0; base < N; base += 1024) {
        int v = (base + t < N) ? g_cnt[base + t] : 0;
        sh[t] = v;
        __syncthreads();
        for (int off = 1; off < 1024; off <<= 1) {
            int tmp = (t >= off) ? sh[t - off] : 0;
            __syncthreads();
            sh[t] += tmp;
            __syncthreads();
        }
        if (base + t < N) g_rowptr[base + t] = carry_s + sh[t] - v;
        __syncthreads();
        if (t == 0) carry_s += sh[1023];
        __syncthreads();
    }
    if (t == 0) g_rowptr[N] = carry_s;
}

__global__ void fill_k(const int* __restrict__ dst, int E) {
    int i = blockIdx.x * blockDim.x + threadIdx.x;
    if (i >= E) return;
    int d = dst[i];
    int slot = atomicAdd(&g_cnt[d], 1);
    g_eid[g_rowptr[d] + slot] = i;
}

__global__ void embed_k(const int* __restrict__ x, const float* __restrict__ emb, int n32) {
    int i = blockIdx.x * blockDim.x + threadIdx.x;
    if (i >= n32) return;
    int n = i >> 5, c = i & 31;
    ((float4*)g_feat)[i] = ((const float4*)emb)[(size_t)x[n] * DV4 + c];
}

__global__ void edge_enc_k(const int* __restrict__ flow, const int* __restrict__ pos,
                           const int* __restrict__ blk, const int* __restrict__ src,
                           const int* __restrict__ dst,
                           const float* __restrict__ fe, const float* __restrict__ pe,
                           const float* __restrict__ be, int e32) {
    int i = blockIdx.x * blockDim.x + threadIdx.x;
    if (i >= e32) return;
    int ed = i >> 5, c = i & 31;
    int cr = (blk[src[ed]] != blk[dst[ed]]) ? 1 : 0;
    float4 a = ((const float4*)fe)[flow[ed] * DV4 + c];
    float4 b = ((const float4*)pe)[pos[ed] * DV4 + c];
    float4 d = ((const float4*)be)[cr * DV4 + c];
    float4 o;
    o.x = a.x + b.x + d.x; o.y = a.y + b.y + d.y;
    o.z = a.z + b.z + d.z; o.w = a.w + b.w + d.w;
    ((float4*)g_e)[i] = o;
}

// ---------------- shared GEMM building blocks (512 thr, 128-row tile) ----------
__device__ __forceinline__ void stage_A(const float* __restrict__ A, float* As,
                                        int row0, int M, int tid) {
    int lane = tid & 31;
#pragma unroll
    for (int it = 0; it < 8; it++) {
        int j = tid + it * 512;
        int r = j >> 5, kc = j & 31;
        int gr = row0 + r;
        float4 av = (gr < M) ? ((const float4*)A)[(size_t)gr * DV4 + kc]
                             : make_float4(0.f, 0.f, 0.f, 0.f);
        float vals[4] = {av.x, av.y, av.z, av.w};
#pragma unroll
        for (int q = 0; q < 4; q++) {
            int i = ((lane >> 3) + q) & 3;   // diagonal order: 4-way instead of 16-way
            As[(kc * 4 + i) * P_AS + r] = vals[i];
        }
    }
}

__device__ __forceinline__ void prefetch_W(const float* __restrict__ W,
                                           unsigned int dst_base, int tid) {
    const float4* W4 = (const float4*)W;
#pragma unroll
    for (int it = 0; it < 8; it++)
        cp16(dst_base + (unsigned)(tid + it * 512) * 16u, W4 + tid + it * 512);
    CP_COMMIT();
}

__device__ __forceinline__ void mainloop(const float* As, const float* Ws,
                                         int rb, int cg, unsigned long long acc[4][4]) {
#pragma unroll
    for (int i = 0; i < 4; i++)
#pragma unroll
        for (int j = 0; j < 4; j++) acc[i][j] = 0ull;
#pragma unroll 4
    for (int k = 0; k < 128; k++) {
        float4 wv = *(const float4*)&Ws[k * 128 + cg * 4];
        unsigned long long wp0 = pack2(wv.x), wp1 = pack2(wv.y);
        unsigned long long wp2 = pack2(wv.z), wp3 = pack2(wv.w);
        const ulonglong2* ap = (const ulonglong2*)&As[k * P_AS + rb];
        ulonglong2 aA = ap[0], aB = ap[1];
        unsigned long long ar0 = aA.x, ar1 = aA.y, ar2 = aB.x, ar3 = aB.y;
        FMA2(acc[0][0], ar0, wp0); FMA2(acc[0][1], ar0, wp1);
        FMA2(acc[0][2], ar0, wp2); FMA2(acc[0][3], ar0, wp3);
        FMA2(acc[1][0], ar1, wp0); FMA2(acc[1][1], ar1, wp1);
        FMA2(acc[1][2], ar1, wp2); FMA2(acc[1][3], ar1, wp3);
        FMA2(acc[2][0], ar2, wp0); FMA2(acc[2][1], ar2, wp1);
        FMA2(acc[2][2], ar2, wp2); FMA2(acc[2][3], ar2, wp3);
        FMA2(acc[3][0], ar3, wp0); FMA2(acc[3][1], ar3, wp1);
        FMA2(acc[3][2], ar3, wp2); FMA2(acc[3][3], ar3, wp3);
    }
}

__device__ __forceinline__ void unpack_acc(unsigned long long acc[4][4],
                                           float lo[4][4], float hi[4][4]) {
#pragma unroll
    for (int i = 0; i < 4; i++)
#pragma unroll
        for (int j = 0; j < 4; j++) {
            unsigned int l32, h32;
            asm("mov.b64 {%0,%1}, %2;" : "=r"(l32), "=r"(h32) : "l"(acc[i][j]));
            lo[i][j] = __uint_as_float(l32);
            hi[i][j] = __uint_as_float(h32);
        }
}

__device__ __forceinline__ void write_plain(float* __restrict__ C, int row0, int rb, int cg,
                                            int M, float lo[4][4], float hi[4][4]) {
#pragma unroll
    for (int i = 0; i < 4; i++) {
        int r = row0 + rb + 2 * i;
        if (r < M)
            ((float4*)C)[(size_t)r * DV4 + cg] = make_float4(lo[i][0], lo[i][1], lo[i][2], lo[i][3]);
        if (r + 1 < M)
            ((float4*)C)[(size_t)(r + 1) * DV4 + cg] = make_float4(hi[i][0], hi[i][1], hi[i][2], hi[i][3]);
    }
}

// ---------- fused node GEMM: q,k,v,P1,P2 from feat; cp.async W ping-pong -------
__global__ void __launch_bounds__(512) gemm_node5_k(
        const float* __restrict__ A,
        const float* __restrict__ W0, const float* __restrict__ W1,
        const float* __restrict__ W2, const float* __restrict__ W3,
        const float* __restrict__ W4,
        float* __restrict__ C0, float* __restrict__ C1, float* __restrict__ C2,
        float* __restrict__ C3, float* __restrict__ C4, int M) {
    extern __shared__ float sm[];
    float* As = sm;                       // 128 x P_AS
    float* Wb = sm + 128 * P_AS;          // 2 x 16384 floats
    unsigned int wbu = (unsigned int)__cvta_generic_to_shared(Wb);
    int tid = threadIdx.x;
    int row0 = blockIdx.x * 128;
    int rb = (tid >> 5) * 8, cg = tid & 31;

    const float* Wp[5] = {W0, W1, W2, W3, W4};
    float* Cp[5] = {C0, C1, C2, C3, C4};

    prefetch_W(Wp[0], wbu, tid);          // into buf 0
    stage_A(A, As, row0, M, tid);

    unsigned long long acc[4][4];
    float lo[4][4], hi[4][4];
#pragma unroll
    for (int p = 0; p < 5; p++) {
        CP_WAIT0();
        __syncthreads();                  // W[p] visible; prior reads of buf[(p+1)&1] done
        if (p + 1 < 5)
            prefetch_W(Wp[p + 1], wbu + ((p + 1) & 1) * (WS_FLOATS * 4), tid);
        mainloop(As, Wb + (p & 1) * WS_FLOATS, rb, cg, acc);
        unpack_acc(acc, lo, hi);
        write_plain(Cp[p], row0, rb, cg, M, lo, hi);
    }
}

// ---- fused edge GEMM (3 passes, ONE staging of e):
//      pass0 Wek -> attention scores (ek never stored)
//      pass1 Wev -> ev
//      pass2 Weu3 -> e = relu(e + e@Weu3 + P1[src] + P2[dst])  (in-place, row-local)
__global__ void __launch_bounds__(512) gemm_edge3_k(
        const float* __restrict__ A, const float* __restrict__ Wek,
        const float* __restrict__ Wev, const float* __restrict__ Weu3,
        float* __restrict__ Cev, float* __restrict__ Ce,
        const float* __restrict__ P1, const float* __restrict__ P2,
        const int* __restrict__ src, const int* __restrict__ dst, int M) {
    extern __shared__ float sm[];
    float* As = sm;
    float* Wb = sm + 128 * P_AS;
    unsigned int wbu = (unsigned int)__cvta_generic_to_shared(Wb);
    int tid = threadIdx.x;
    int row0 = blockIdx.x * 128;
    int rb = (tid >> 5) * 8, cg = tid & 31;

    const float* Wp[3] = {Wek, Wev, Weu3};

    prefetch_W(Wp[0], wbu, tid);
    stage_A(A, As, row0, M, tid);

    unsigned long long acc[4][4];
    float lo[4][4], hi[4][4];
#pragma unroll
    for (int p = 0; p < 3; p++) {
        CP_WAIT0();
        __syncthreads();
        if (p + 1 < 3)
            prefetch_W(Wp[p + 1], wbu + ((p + 1) & 1) * (WS_FLOATS * 4), tid);
        mainloop(As, Wb + (p & 1) * WS_FLOATS, rb, cg, acc);
        unpack_acc(acc, lo, hi);

        if (p == 0) {
            // scores epilogue: per-edge q[dst]·(k[src]+ek)
#pragma unroll
            for (int ri = 0; ri < 8; ri++) {
                int er = row0 + rb + ri;
                if (er < M) {
                    int i = ri >> 1;
                    float e0 = (ri & 1) ? hi[i][0] : lo[i][0];
                    float e1 = (ri & 1) ? hi[i][1] : lo[i][1];
                    float e2 = (ri & 1) ? hi[i][2] : lo[i][2];
                    float e3 = (ri & 1) ? hi[i][3] : lo[i][3];
                    int s = src[er], d = dst[er];
                    float4 qv = ((const float4*)g_q)[(size_t)d * DV4 + cg];
                    float4 kv = ((const float4*)g_k)[(size_t)s * DV4 + cg];
                    float pv = qv.x * (kv.x + e0) + qv.y * (kv.y + e1)
                             + qv.z * (kv.z + e2) + qv.w * (kv.w + e3);
                    pv += __shfl_down_sync(0xffffffffu, pv, 4, 8);
                    pv += __shfl_down_sync(0xffffffffu, pv, 2, 8);
                    pv += __shfl_down_sync(0xffffffffu, pv, 1, 8);
                    if ((cg & 7) == 0)
                        g_sc[(size_t)er * 4 + (cg >> 3)] = pv * 0.17677669529663689f;
                }
            }
        } else if (p == 1) {
            write_plain(Cev, row0, rb, cg, M, lo, hi);
        } else {
            // e-update epilogue (in-place; this block's rows already staged in As)
#pragma unroll
            for (int ri = 0; ri < 8; ri++) {
                int r = row0 + rb + ri;
                if (r >= M) continue;
                int i = ri >> 1;
                float x = (ri & 1) ? hi[i][0] : lo[i][0];
                float y = (ri & 1) ? hi[i][1] : lo[i][1];
                float z = (ri & 1) ? hi[i][2] : lo[i][2];
                float w = (ri & 1) ? hi[i][3] : lo[i][3];
                float4 res = ((const float4*)Ce)[(size_t)r * DV4 + cg];
                int s = src[r], dd = dst[r];
                float4 p1 = ((const float4*)P1)[(size_t)s * DV4 + cg];
                float4 p2 = ((const float4*)P2)[(size_t)dd * DV4 + cg];
                x = fmaxf(x + res.x + p1.x + p2.x, 0.f);
                y = fmaxf(y + res.y + p1.y + p2.y, 0.f);
                z = fmaxf(z + res.z + p1.z + p2.z, 0.f);
                w = fmaxf(w + res.w + p1.w + p2.w, 0.f);
                ((float4*)Ce)[(size_t)r * DV4 + cg] = make_float4(x, y, z, w);
            }
        }
    }
}

// ------- single-pass GEMM with relu residual epilogue: C = relu(R + A@W) -------
__global__ void __launch_bounds__(512) gemm_epi_k(
        const float* __restrict__ A, const float* __restrict__ W,
        float* __restrict__ C, const float* __restrict__ R, int M) {
    extern __shared__ float sm[];
    float* As = sm;
    float* Ws = sm + 128 * P_AS;
    unsigned int wsu = (unsigned int)__cvta_generic_to_shared(Ws);
    int tid = threadIdx.x;
    int row0 = blockIdx.x * 128;
    int rb = (tid >> 5) * 8, cg = tid & 31;

    prefetch_W(W, wsu, tid);
    stage_A(A, As, row0, M, tid);
    CP_WAIT0();
    __syncthreads();

    unsigned long long acc[4][4];
    mainloop(As, Ws, rb, cg, acc);
    float lo[4][4], hi[4][4];
    unpack_acc(acc, lo, hi);
#pragma unroll
    for (int ri = 0; ri < 8; ri++) {
        int r = row0 + rb + ri;
        if (r >= M) continue;
        int i = ri >> 1;
        float x = (ri & 1) ? hi[i][0] : lo[i][0];
        float y = (ri & 1) ? hi[i][1] : lo[i][1];
        float z = (ri & 1) ? hi[i][2] : lo[i][2];
        float w = (ri & 1) ? hi[i][3] : lo[i][3];
        float4 res = ((const float4*)R)[(size_t)r * DV4 + cg];
        x = fmaxf(x + res.x, 0.f); y = fmaxf(y + res.y, 0.f);
        z = fmaxf(z + res.z, 0.f); w = fmaxf(w + res.w, 0.f);
        ((float4*)C)[(size_t)r * DV4 + cg] = make_float4(x, y, z, w);
    }
}

// ---------------- attention kernels ----------------
__global__ void stats_k(int N) {
    int n = blockIdx.x * blockDim.x + threadIdx.x;
    if (n >= N) return;
    int b = g_rowptr[n], e = g_rowptr[n + 1];
    float m0 = -1e30f, m1 = -1e30f, m2 = -1e30f, m3 = -1e30f;
    float s0 = 0.f, s1 = 0.f, s2 = 0.f, s3 = 0.f;
    for (int j = b; j < e; j++) {
        int eid = g_eid[j];
        float4 sc = ((const float4*)g_sc)[eid];
        float nm;
        nm = fmaxf(m0, sc.x); s0 = s0 * expf(m0 - nm) + expf(sc.x - nm); m0 = nm;
        nm = fmaxf(m1, sc.y); s1 = s1 * expf(m1 - nm) + expf(sc.y - nm); m1 = nm;
        nm = fmaxf(m2, sc.z); s2 = s2 * expf(m2 - nm) + expf(sc.z - nm); m2 = nm;
        nm = fmaxf(m3, sc.w); s3 = s3 * expf(m3 - nm) + expf(sc.w - nm); m3 = nm;
    }
    g_m[n * 4 + 0] = m0; g_m[n * 4 + 1] = m1; g_m[n * 4 + 2] = m2; g_m[n * 4 + 3] = m3;
    g_den[n * 4 + 0] = s0; g_den[n * 4 + 1] = s1; g_den[n * 4 + 2] = s2; g_den[n * 4 + 3] = s3;
}

__global__ void agg_k(const int* __restrict__ src, int N) {   // warp per node
    int gt = blockIdx.x * blockDim.x + threadIdx.x;
    int n = gt >> 5, l = gt & 31;
    if (n >= N) return;
    int h = l >> 3;
    float m = g_m[n * 4 + h];
    float inv = 1.0f / (g_den[n * 4 + h] + 1e-16f);
    int b = g_rowptr[n], e = g_rowptr[n + 1];
    float4 acc = make_float4(0.f, 0.f, 0.f, 0.f);
    for (int j = b; j < e; j++) {
        int eid = g_eid[j];
        int s = src[eid];
        float a = expf(g_sc[(size_t)eid * 4 + h] - m) * inv;
        float4 v4 = ((const float4*)g_v)[(size_t)s * DV4 + l];
        float4 ev4 = ((const float4*)g_ev)[(size_t)eid * DV4 + l];
        acc.x += a * (v4.x + ev4.x);
        acc.y += a * (v4.y + ev4.y);
        acc.z += a * (v4.z + ev4.z);
        acc.w += a * (v4.w + ev4.w);
    }
    ((float4*)g_agg)[(size_t)n * DV4 + l] = acc;
}

// ---------------- readout ----------------
__global__ void node_scatter_k(const int* __restrict__ nt, const int* __restrict__ batch, int n32) {
    int i = blockIdx.x * blockDim.x + threadIdx.x;
    if (i >= n32) return;
    int n = i >> 5, c = i & 31;
    if (nt[n] != 0) return;
    int g = batch[n];
    float4 f = ((const float4*)g_feat)[i];
    atomicAdd(&g_gagg[g * DD + c * 4 + 0], f.x);
    atomicAdd(&g_gagg[g * DD + c * 4 + 1], f.y);
    atomicAdd(&g_gagg[g * DD + c * 4 + 2], f.z);
    atomicAdd(&g_gagg[g * DD + c * 4 + 3], f.w);
    if (c == 0) atomicAdd(&g_gcnt[g], 1.0f);
}

__global__ void edge_scatter_k(const int* __restrict__ src, const int* __restrict__ batch, int e32) {
    int i = blockIdx.x * blockDim.x + threadIdx.x;
    if (i >= e32) return;
    int ed = i >> 5, c = i & 31;
    int g = batch[src[ed]];
    float4 f = ((const float4*)g_e)[i];
    atomicAdd(&g_eagg[g * DD + c * 4 + 0], f.x);
    atomicAdd(&g_eagg[g * DD + c * 4 + 1], f.y);
    atomicAdd(&g_eagg[g * DD + c * 4 + 2], f.z);
    atomicAdd(&g_eagg[g * DD + c * 4 + 3], f.w);
    if (c == 0) atomicAdd(&g_ecnt[g], 1.0f);
}

__global__ void final_k(const float* __restrict__ QW1, const float* __restrict__ Qb1,
                        const float* __restrict__ QW2, const float* __restrict__ Qb2,
                        float* __restrict__ out, int A) {
    int g = blockIdx.x;
    int t = threadIdx.x;
    __shared__ float ga[256];
    __shared__ float hh[128];
    __shared__ float lg[128];
    __shared__ float lse_s;
    float ncnt = fmaxf(g_gcnt[g], 1.0f);
    float ecnt = fmaxf(g_ecnt[g], 1.0f);
    if (t < 128) ga[t] = g_gagg[g * DD + t] / ncnt;
    else         ga[t] = g_eagg[g * DD + (t - 128)] / ecnt;
    __syncthreads();
    if (t < 128) {
        float acc = Qb1[t];
        for (int j = 0; j < 256; j++) acc += ga[j] * QW1[j * 128 + t];
        hh[t] = fmaxf(acc, 0.f);
    }
    __syncthreads();
    if (t < A) {
        float acc = Qb2[t];
        for (int j = 0; j < 128; j++) acc += hh[j] * QW2[j * A + t];
        lg[t] = acc;
    }
    __syncthreads();
    if (t == 0) {
        float m = -1e30f;
        for (int i = 0; i < A; i++) m = fmaxf(m, lg[i]);
        float s = 0.f;
        for (int i = 0; i < A; i++) s += expf(lg[i] - m);
        lse_s = logf(s) + m;
    }
    __syncthreads();
    if (t < A) out[g * A + t] = lg[t] - lse_s;
}

// ---------------- host launcher ----------------
extern "C" void kernel_launch(void* const* d_in, const int* in_sizes, int n_in,
                              void* d_out, int out_size) {
    const int*   x         = (const int*)d_in[0];
    const int*   node_type = (const int*)d_in[1];
    const int*   batch     = (const int*)d_in[2];
    const int*   eix       = (const int*)d_in[3];
    const int*   flow      = (const int*)d_in[4];
    const int*   pos       = (const int*)d_in[5];
    const int*   blk       = (const int*)d_in[6];
    const float* emb       = (const float*)d_in[8];
    const float* fe        = (const float*)d_in[9];
    const float* pe        = (const float*)d_in[10];
    const float* be        = (const float*)d_in[11];
    const float* Wq        = (const float*)d_in[12];
    const float* Wk        = (const float*)d_in[13];
    const float* Wv        = (const float*)d_in[14];
    const float* Wek       = (const float*)d_in[15];
    const float* Wev       = (const float*)d_in[16];
    const float* Wo        = (const float*)d_in[17];
    const float* Weu       = (const float*)d_in[18];
    const float* QW1       = (const float*)d_in[19];
    const float* Qb1       = (const float*)d_in[20];
    const float* QW2       = (const float*)d_in[21];
    const float* Qb2       = (const float*)d_in[22];

    int N = in_sizes[0];
    int E = in_sizes[4];
    int L = in_sizes[12] / (128 * 128);
    int A = in_sizes[22];
    const int* src = eix;
    const int* dst = eix + E;

    float *p_feat, *p_q, *p_k, *p_v, *p_agg, *p_P1, *p_P2, *p_e, *p_ev;
    float *p_gagg, *p_eagg, *p_gcnt, *p_ecnt;
    int *p_cnt;
    cudaGetSymbolAddress((void**)&p_feat, g_feat);
    cudaGetSymbolAddress((void**)&p_q, g_q);
    cudaGetSymbolAddress((void**)&p_k, g_k);
    cudaGetSymbolAddress((void**)&p_v, g_v);
    cudaGetSymbolAddress((void**)&p_agg, g_agg);
    cudaGetSymbolAddress((void**)&p_P1, g_P1);
    cudaGetSymbolAddress((void**)&p_P2, g_P2);
    cudaGetSymbolAddress((void**)&p_e, g_e);
    cudaGetSymbolAddress((void**)&p_ev, g_ev);
    cudaGetSymbolAddress((void**)&p_cnt, g_cnt);
    cudaGetSymbolAddress((void**)&p_gagg, g_gagg);
    cudaGetSymbolAddress((void**)&p_eagg, g_eagg);
    cudaGetSymbolAddress((void**)&p_gcnt, g_gcnt);
    cudaGetSymbolAddress((void**)&p_ecnt, g_ecnt);

    cudaFuncSetAttribute(gemm_node5_k, cudaFuncAttributeMaxDynamicSharedMemorySize, SMEM_DB);
    cudaFuncSetAttribute(gemm_edge3_k, cudaFuncAttributeMaxDynamicSharedMemorySize, SMEM_DB);
    cudaFuncSetAttribute(gemm_epi_k,   cudaFuncAttributeMaxDynamicSharedMemorySize, SMEM_SB);

    const int T = 256;
    // CSR build (dst-grouped), once per call; zeroing via memset (not kernels)
    cudaMemsetAsync(p_cnt, 0, (size_t)N * 4);
    hist_k<<<ceil_div(E, T), T>>>(dst, E);
    scan_k<<<1, 1024>>>(N);
    cudaMemsetAsync(p_cnt, 0, (size_t)N * 4);
    fill_k<<<ceil_div(E, T), T>>>(dst, E);
    // input encodings
    embed_k<<<ceil_div(N * 32, T), T>>>(x, emb, N * 32);
    edge_enc_k<<<ceil_div(E * 32, T), T>>>(flow, pos, blk, src, dst, fe, pe, be, E * 32);

    int gN = ceil_div(N, 128), gE = ceil_div(E, 128);
    for (int l = 0; l < L; l++) {
        const float* wq  = Wq  + (size_t)l * 16384;
        const float* wk  = Wk  + (size_t)l * 16384;
        const float* wv  = Wv  + (size_t)l * 16384;
        const float* wek = Wek + (size_t)l * 16384;
        const float* wev = Wev + (size_t)l * 16384;
        const float* wo  = Wo  + (size_t)l * 16384;
        const float* weu = Weu + (size_t)l * 49152;

        // q,k,v,P1,P2 from feat in ONE staged pass set (W double-buffered)
        gemm_node5_k<<<gN, 512, SMEM_DB>>>(p_feat, wq, wk, wv, weu, weu + 16384,
                                           p_q, p_k, p_v, p_P1, p_P2, N);
        // scores + ev + in-place e-update from ONE staging of e
        gemm_edge3_k<<<gE, 512, SMEM_DB>>>(p_e, wek, wev, weu + 32768,
                                           p_ev, p_e, p_P1, p_P2, src, dst, E);

        stats_k<<<ceil_div(N, T), T>>>(N);
        agg_k<<<ceil_div(N * 32, T), T>>>(src, N);

        // feat = relu(feat + agg@Wo)
        gemm_epi_k<<<gN, 512, SMEM_SB>>>(p_agg, wo, p_feat, p_feat, N);
    }

    // readout
    cudaMemsetAsync(p_gagg, 0, (size_t)GMAX * DD * 4);
    cudaMemsetAsync(p_eagg, 0, (size_t)GMAX * DD * 4);
    cudaMemsetAsync(p_gcnt, 0, (size_t)GMAX * 4);
    cudaMemsetAsync(p_ecnt, 0, (size_t)GMAX * 4);
    node_scatter_k<<<ceil_div(N * 32, T), T>>>(node_type, batch, N * 32);
    edge_scatter_k<<<ceil_div(E * 32, T), T>>>(src, batch, E * 32);
    final_k<<<GMAX, T>>>(QW1, Qb1, QW2, Qb2, (float*)d_out, A);
}

// round 13
// speedup vs baseline: 1.2686x; 1.0500x over previous
#include <cuda_runtime.h>
#include <math.h>

#define DD   128
#define DV4  32
#define NH   4
#define GMAX 64
#define NMAX 100000
#define EMAX 500000
#define P_AS 132
#define WS_FLOATS 16384
#define SMEM_DB ((128*P_AS + 2*WS_FLOATS)*4)   // 198,656 B
#define SMEM_SB ((128*P_AS + 1*WS_FLOATS)*4)   // 133,120 B

// ---------------- device scratch (static, no allocation) ----------------
__device__ float g_feat[NMAX*DD];
__device__ float g_q[NMAX*DD];
__device__ float g_k[NMAX*DD];
__device__ float g_v[NMAX*DD];
__device__ float g_agg[NMAX*DD];
__device__ float g_P1[NMAX*DD];
__device__ float g_P2[NMAX*DD];
__device__ float g_e[EMAX*DD];
__device__ float g_ev[EMAX*DD];
__device__ float g_sc[EMAX*NH];
__device__ float g_m[NMAX*NH];
__device__ float g_den[NMAX*NH];
__device__ int   g_cnt[NMAX];
__device__ int   g_rowptr[NMAX+1];
__device__ int   g_eid[EMAX];
__device__ float g_gagg[GMAX*DD];
__device__ float g_eagg[GMAX*DD];
__device__ float g_gcnt[GMAX];
__device__ float g_ecnt[GMAX];

static inline int ceil_div(int a, int b) { return (a + b - 1) / b; }

__device__ __forceinline__ unsigned long long pack2(float x) {
    unsigned long long r;
    asm("mov.b64 %0, {%1, %1};" : "=l"(r) : "f"(x));
    return r;
}
#define FMA2(d, a, b) asm("fma.rn.f32x2 %0, %1, %2, %0;" : "+l"(d) : "l"(a), "l"(b))

__device__ __forceinline__ void cp16(unsigned int dst, const void* src) {
    asm volatile("cp.async.cg.shared.global [%0], [%1], 16;" :: "r"(dst), "l"(src));
}
#define CP_COMMIT() asm volatile("cp.async.commit_group;")
#define CP_WAIT0()  asm volatile("cp.async.wait_group 0;")

// ---------------- setup kernels ----------------
__global__ void hist_k(const int* __restrict__ dst, int E) {
    int i = blockIdx.x * blockDim.x + threadIdx.x;
    if (i < E) atomicAdd(&g_cnt[dst[i]], 1);
}

// single block; also re-zeroes g_cnt for fill_k
__global__ void scan_k(int N) {
    __shared__ int sh[1024];
    __shared__ int carry_s;
    int t = threadIdx.x;
    if (t == 0) carry_s = 0;
    __syncthreads();
    for (int base = 0; base < N; base += 1024) {
        int v = (base + t < N) ? g_cnt[base + t] : 0;
        sh[t] = v;
        __syncthreads();
        for (int off = 1; off < 1024; off <<= 1) {
            int tmp = (t >= off) ? sh[t - off] : 0;
            __syncthreads();
            sh[t] += tmp;
            __syncthreads();
        }
        if (base + t < N) {
            g_rowptr[base + t] = carry_s + sh[t] - v;
            g_cnt[base + t] = 0;
        }
        __syncthreads();
        if (t == 0) carry_s += sh[1023];
        __syncthreads();
    }
    if (t == 0) g_rowptr[N] = carry_s;
}

__global__ void fill_k(const int* __restrict__ dst, int E) {
    int i = blockIdx.x * blockDim.x + threadIdx.x;
    if (i >= E) return;
    int d = dst[i];
    int slot = atomicAdd(&g_cnt[d], 1);
    g_eid[g_rowptr[d] + slot] = i;
}

__global__ void embed_k(const int* __restrict__ x, const float* __restrict__ emb, int n32) {
    int i = blockIdx.x * blockDim.x + threadIdx.x;
    if (i >= n32) return;
    int n = i >> 5, c = i & 31;
    ((float4*)g_feat)[i] = ((const float4*)emb)[(size_t)x[n] * DV4 + c];
}

__global__ void edge_enc_k(const int* __restrict__ flow, const int* __restrict__ pos,
                           const int* __restrict__ blk, const int* __restrict__ src,
                           const int* __restrict__ dst,
                           const float* __restrict__ fe, const float* __restrict__ pe,
                           const float* __restrict__ be, int e32) {
    int i = blockIdx.x * blockDim.x + threadIdx.x;
    if (i >= e32) return;
    int ed = i >> 5, c = i & 31;
    int cr = (blk[src[ed]] != blk[dst[ed]]) ? 1 : 0;
    float4 a = ((const float4*)fe)[flow[ed] * DV4 + c];
    float4 b = ((const float4*)pe)[pos[ed] * DV4 + c];
    float4 d = ((const float4*)be)[cr * DV4 + c];
    float4 o;
    o.x = a.x + b.x + d.x; o.y = a.y + b.y + d.y;
    o.z = a.z + b.z + d.z; o.w = a.w + b.w + d.w;
    ((float4*)g_e)[i] = o;
}

// ------------- GEMM building blocks (512 thr, 128-row tile) -------------------
// Stage A transposed: 4 rows/thread, register transpose, STS.128 (4-way max).
__device__ __forceinline__ void stage_A(const float* __restrict__ A, float* As,
                                        int row0, int M, int tid) {
    int kc = tid & 31;
#pragma unroll
    for (int g = 0; g < 2; g++) {
        int R = (((tid >> 5) & 15) + g * 16) * 4;   // 0..124
        int gr = row0 + R;
        float4 z = make_float4(0.f, 0.f, 0.f, 0.f);
        float4 a0 = z, a1 = z, a2 = z, a3 = z;
        if (gr + 3 < M) {
            a0 = ((const float4*)A)[(size_t)(gr + 0) * DV4 + kc];
            a1 = ((const float4*)A)[(size_t)(gr + 1) * DV4 + kc];
            a2 = ((const float4*)A)[(size_t)(gr + 2) * DV4 + kc];
            a3 = ((const float4*)A)[(size_t)(gr + 3) * DV4 + kc];
        } else {
            if (gr + 0 < M) a0 = ((const float4*)A)[(size_t)(gr + 0) * DV4 + kc];
            if (gr + 1 < M) a1 = ((const float4*)A)[(size_t)(gr + 1) * DV4 + kc];
            if (gr + 2 < M) a2 = ((const float4*)A)[(size_t)(gr + 2) * DV4 + kc];
            if (gr + 3 < M) a3 = ((const float4*)A)[(size_t)(gr + 3) * DV4 + kc];
        }
        *(float4*)&As[(4 * kc + 0) * P_AS + R] = make_float4(a0.x, a1.x, a2.x, a3.x);
        *(float4*)&As[(4 * kc + 1) * P_AS + R] = make_float4(a0.y, a1.y, a2.y, a3.y);
        *(float4*)&As[(4 * kc + 2) * P_AS + R] = make_float4(a0.z, a1.z, a2.z, a3.z);
        *(float4*)&As[(4 * kc + 3) * P_AS + R] = make_float4(a0.w, a1.w, a2.w, a3.w);
    }
}

__device__ __forceinline__ void prefetch_W(const float* __restrict__ W,
                                           unsigned int dst_base, int tid) {
    const float4* W4 = (const float4*)W;
#pragma unroll
    for (int it = 0; it < 8; it++)
        cp16(dst_base + (unsigned)(tid + it * 512) * 16u, W4 + tid + it * 512);
    CP_COMMIT();
}

__device__ __forceinline__ void mainloop(const float* As, const float* Ws,
                                         int rb, int cg, unsigned long long acc[4][4]) {
#pragma unroll
    for (int i = 0; i < 4; i++)
#pragma unroll
        for (int j = 0; j < 4; j++) acc[i][j] = 0ull;
#pragma unroll 4
    for (int k = 0; k < 128; k++) {
        float4 wv = *(const float4*)&Ws[k * 128 + cg * 4];
        unsigned long long wp0 = pack2(wv.x), wp1 = pack2(wv.y);
        unsigned long long wp2 = pack2(wv.z), wp3 = pack2(wv.w);
        const ulonglong2* ap = (const ulonglong2*)&As[k * P_AS + rb];
        ulonglong2 aA = ap[0], aB = ap[1];
        unsigned long long ar0 = aA.x, ar1 = aA.y, ar2 = aB.x, ar3 = aB.y;
        FMA2(acc[0][0], ar0, wp0); FMA2(acc[0][1], ar0, wp1);
        FMA2(acc[0][2], ar0, wp2); FMA2(acc[0][3], ar0, wp3);
        FMA2(acc[1][0], ar1, wp0); FMA2(acc[1][1], ar1, wp1);
        FMA2(acc[1][2], ar1, wp2); FMA2(acc[1][3], ar1, wp3);
        FMA2(acc[2][0], ar2, wp0); FMA2(acc[2][1], ar2, wp1);
        FMA2(acc[2][2], ar2, wp2); FMA2(acc[2][3], ar2, wp3);
        FMA2(acc[3][0], ar3, wp0); FMA2(acc[3][1], ar3, wp1);
        FMA2(acc[3][2], ar3, wp2); FMA2(acc[3][3], ar3, wp3);
    }
}

__device__ __forceinline__ void unpack_acc(unsigned long long acc[4][4],
                                           float lo[4][4], float hi[4][4]) {
#pragma unroll
    for (int i = 0; i < 4; i++)
#pragma unroll
        for (int j = 0; j < 4; j++) {
            unsigned int l32, h32;
            asm("mov.b64 {%0,%1}, %2;" : "=r"(l32), "=r"(h32) : "l"(acc[i][j]));
            lo[i][j] = __uint_as_float(l32);
            hi[i][j] = __uint_as_float(h32);
        }
}

__device__ __forceinline__ void write_plain(float* __restrict__ C, int row0, int rb, int cg,
                                            int M, float lo[4][4], float hi[4][4]) {
#pragma unroll
    for (int i = 0; i < 4; i++) {
        int r = row0 + rb + 2 * i;
        if (r < M)
            ((float4*)C)[(size_t)r * DV4 + cg] = make_float4(lo[i][0], lo[i][1], lo[i][2], lo[i][3]);
        if (r + 1 < M)
            ((float4*)C)[(size_t)(r + 1) * DV4 + cg] = make_float4(hi[i][0], hi[i][1], hi[i][2], hi[i][3]);
    }
}

// restage this thread's result tile (rows rb..rb+7, cols 4cg..4cg+3) into As
__device__ __forceinline__ void restage_regs(float* As, int rb, int cg,
                                             float lo[4][4], float hi[4][4]) {
#pragma unroll
    for (int i = 0; i < 4; i++) {
        *(float4*)&As[(4 * cg + i) * P_AS + rb]     = make_float4(lo[0][i], hi[0][i], lo[1][i], hi[1][i]);
        *(float4*)&As[(4 * cg + i) * P_AS + rb + 4] = make_float4(lo[2][i], hi[2][i], lo[3][i], hi[3][i]);
    }
}

// ---- node GEMM: optional pre-pass feat=relu(feat+agg@Wo), then q,k,v,P1,P2 ----
__global__ void __launch_bounds__(512) gemm_node6_k(
        const float* __restrict__ Agg, const float* __restrict__ Wo,
        float* __restrict__ Feat,
        const float* __restrict__ Wq, const float* __restrict__ Wk,
        const float* __restrict__ Wv, const float* __restrict__ Wa,
        const float* __restrict__ Wb,
        float* __restrict__ Cq, float* __restrict__ Ck, float* __restrict__ Cv,
        float* __restrict__ Ca, float* __restrict__ Cb, int M, int do_pre) {
    extern __shared__ float sm[];
    float* As = sm;
    float* Wb2 = sm + 128 * P_AS;
    unsigned int wbu = (unsigned int)__cvta_generic_to_shared(Wb2);
    int tid = threadIdx.x;
    int row0 = blockIdx.x * 128;
    int rb = (tid >> 5) * 8, cg = tid & 31;

    const float* Wl[6];
    float* Cl[6];
    int np;
    if (do_pre) {
        Wl[0] = Wo; Wl[1] = Wq; Wl[2] = Wk; Wl[3] = Wv; Wl[4] = Wa; Wl[5] = Wb;
        Cl[0] = Feat; Cl[1] = Cq; Cl[2] = Ck; Cl[3] = Cv; Cl[4] = Ca; Cl[5] = Cb;
        np = 6;
    } else {
        Wl[0] = Wq; Wl[1] = Wk; Wl[2] = Wv; Wl[3] = Wa; Wl[4] = Wb;
        Cl[0] = Cq; Cl[1] = Ck; Cl[2] = Cv; Cl[3] = Ca; Cl[4] = Cb;
        np = 5;
    }

    prefetch_W(Wl[0], wbu, tid);
    stage_A(do_pre ? Agg : Feat, As, row0, M, tid);

    unsigned long long acc[4][4];
    float lo[4][4], hi[4][4];
    for (int p = 0; p < np; p++) {
        CP_WAIT0();
        __syncthreads();
        if (p + 1 < np)
            prefetch_W(Wl[p + 1], wbu + ((p + 1) & 1) * (WS_FLOATS * 4), tid);
        mainloop(As, Wb2 + (p & 1) * WS_FLOATS, rb, cg, acc);
        unpack_acc(acc, lo, hi);
        if (do_pre && p == 0) {
            // feat = relu(feat + agg@Wo): residual add, write global, restage As
#pragma unroll
            for (int i = 0; i < 4; i++) {
                int r = row0 + rb + 2 * i;
                if (r < M) {
                    float4 f = ((const float4*)Feat)[(size_t)r * DV4 + cg];
                    lo[i][0] = fmaxf(lo[i][0] + f.x, 0.f);
                    lo[i][1] = fmaxf(lo[i][1] + f.y, 0.f);
                    lo[i][2] = fmaxf(lo[i][2] + f.z, 0.f);
                    lo[i][3] = fmaxf(lo[i][3] + f.w, 0.f);
                }
                if (r + 1 < M) {
                    float4 f = ((const float4*)Feat)[(size_t)(r + 1) * DV4 + cg];
                    hi[i][0] = fmaxf(hi[i][0] + f.x, 0.f);
                    hi[i][1] = fmaxf(hi[i][1] + f.y, 0.f);
                    hi[i][2] = fmaxf(hi[i][2] + f.z, 0.f);
                    hi[i][3] = fmaxf(hi[i][3] + f.w, 0.f);
                }
            }
            write_plain(Feat, row0, rb, cg, M, lo, hi);
            __syncthreads();                 // all warps done reading As(agg)
            restage_regs(As, rb, cg, lo, hi); // As := new feat tile
            // pass 1's CP_WAIT0+sync orders restage before next mainloop
        } else {
            write_plain(Cl[p], row0, rb, cg, M, lo, hi);
        }
    }
}

// ---- fused edge GEMM (3 passes, ONE staging of e) ----
__global__ void __launch_bounds__(512) gemm_edge3_k(
        const float* __restrict__ A, const float* __restrict__ Wek,
        const float* __restrict__ Wev, const float* __restrict__ Weu3,
        float* __restrict__ Cev, float* __restrict__ Ce,
        const float* __restrict__ P1, const float* __restrict__ P2,
        const int* __restrict__ src, const int* __restrict__ dst, int M) {
    extern __shared__ float sm[];
    float* As = sm;
    float* Wb2 = sm + 128 * P_AS;
    unsigned int wbu = (unsigned int)__cvta_generic_to_shared(Wb2);
    int tid = threadIdx.x;
    int row0 = blockIdx.x * 128;
    int rb = (tid >> 5) * 8, cg = tid & 31;

    const float* Wl[3] = {Wek, Wev, Weu3};

    prefetch_W(Wl[0], wbu, tid);
    stage_A(A, As, row0, M, tid);

    unsigned long long acc[4][4];
    float lo[4][4], hi[4][4];
#pragma unroll
    for (int p = 0; p < 3; p++) {
        CP_WAIT0();
        __syncthreads();
        if (p + 1 < 3)
            prefetch_W(Wl[p + 1], wbu + ((p + 1) & 1) * (WS_FLOATS * 4), tid);
        mainloop(As, Wb2 + (p & 1) * WS_FLOATS, rb, cg, acc);
        unpack_acc(acc, lo, hi);

        if (p == 0) {
#pragma unroll
            for (int ri = 0; ri < 8; ri++) {
                int er = row0 + rb + ri;
                if (er < M) {
                    int i = ri >> 1;
                    float e0 = (ri & 1) ? hi[i][0] : lo[i][0];
                    float e1 = (ri & 1) ? hi[i][1] : lo[i][1];
                    float e2 = (ri & 1) ? hi[i][2] : lo[i][2];
                    float e3 = (ri & 1) ? hi[i][3] : lo[i][3];
                    int s = src[er], d = dst[er];
                    float4 qv = ((const float4*)g_q)[(size_t)d * DV4 + cg];
                    float4 kv = ((const float4*)g_k)[(size_t)s * DV4 + cg];
                    float pv = qv.x * (kv.x + e0) + qv.y * (kv.y + e1)
                             + qv.z * (kv.z + e2) + qv.w * (kv.w + e3);
                    pv += __shfl_down_sync(0xffffffffu, pv, 4, 8);
                    pv += __shfl_down_sync(0xffffffffu, pv, 2, 8);
                    pv += __shfl_down_sync(0xffffffffu, pv, 1, 8);
                    if ((cg & 7) == 0)
                        g_sc[(size_t)er * 4 + (cg >> 3)] = pv * 0.17677669529663689f;
                }
            }
        } else if (p == 1) {
            write_plain(Cev, row0, rb, cg, M, lo, hi);
        } else {
#pragma unroll
            for (int ri = 0; ri < 8; ri++) {
                int r = row0 + rb + ri;
                if (r >= M) continue;
                int i = ri >> 1;
                float x = (ri & 1) ? hi[i][0] : lo[i][0];
                float y = (ri & 1) ? hi[i][1] : lo[i][1];
                float z = (ri & 1) ? hi[i][2] : lo[i][2];
                float w = (ri & 1) ? hi[i][3] : lo[i][3];
                float4 res = ((const float4*)Ce)[(size_t)r * DV4 + cg];
                int s = src[r], dd = dst[r];
                float4 p1 = ((const float4*)P1)[(size_t)s * DV4 + cg];
                float4 p2 = ((const float4*)P2)[(size_t)dd * DV4 + cg];
                x = fmaxf(x + res.x + p1.x + p2.x, 0.f);
                y = fmaxf(y + res.y + p1.y + p2.y, 0.f);
                z = fmaxf(z + res.z + p1.z + p2.z, 0.f);
                w = fmaxf(w + res.w + p1.w + p2.w, 0.f);
                ((float4*)Ce)[(size_t)r * DV4 + cg] = make_float4(x, y, z, w);
            }
        }
    }
}

// ---- single-pass GEMM, relu residual: C = relu(R + A@W)  (final layer only) ----
__global__ void __launch_bounds__(512) gemm_epi_k(
        const float* __restrict__ A, const float* __restrict__ W,
        float* __restrict__ C, const float* __restrict__ Rr, int M) {
    extern __shared__ float sm[];
    float* As = sm;
    float* Ws = sm + 128 * P_AS;
    unsigned int wsu = (unsigned int)__cvta_generic_to_shared(Ws);
    int tid = threadIdx.x;
    int row0 = blockIdx.x * 128;
    int rb = (tid >> 5) * 8, cg = tid & 31;

    prefetch_W(W, wsu, tid);
    stage_A(A, As, row0, M, tid);
    CP_WAIT0();
    __syncthreads();

    unsigned long long acc[4][4];
    mainloop(As, Ws, rb, cg, acc);
    float lo[4][4], hi[4][4];
    unpack_acc(acc, lo, hi);
#pragma unroll
    for (int ri = 0; ri < 8; ri++) {
        int r = row0 + rb + ri;
        if (r >= M) continue;
        int i = ri >> 1;
        float x = (ri & 1) ? hi[i][0] : lo[i][0];
        float y = (ri & 1) ? hi[i][1] : lo[i][1];
        float z = (ri & 1) ? hi[i][2] : lo[i][2];
        float w = (ri & 1) ? hi[i][3] : lo[i][3];
        float4 res = ((const float4*)Rr)[(size_t)r * DV4 + cg];
        x = fmaxf(x + res.x, 0.f); y = fmaxf(y + res.y, 0.f);
        z = fmaxf(z + res.z, 0.f); w = fmaxf(w + res.w, 0.f);
        ((float4*)C)[(size_t)r * DV4 + cg] = make_float4(x, y, z, w);
    }
}

// ---------------- attention kernels ----------------
__global__ void stats_k(int N) {
    int n = blockIdx.x * blockDim.x + threadIdx.x;
    if (n >= N) return;
    int b = g_rowptr[n], e = g_rowptr[n + 1];
    float m0 = -1e30f, m1 = -1e30f, m2 = -1e30f, m3 = -1e30f;
    float s0 = 0.f, s1 = 0.f, s2 = 0.f, s3 = 0.f;
    for (int j = b; j < e; j++) {
        int eid = g_eid[j];
        float4 sc = ((const float4*)g_sc)[eid];
        float nm;
        nm = fmaxf(m0, sc.x); s0 = s0 * expf(m0 - nm) + expf(sc.x - nm); m0 = nm;
        nm = fmaxf(m1, sc.y); s1 = s1 * expf(m1 - nm) + expf(sc.y - nm); m1 = nm;
        nm = fmaxf(m2, sc.z); s2 = s2 * expf(m2 - nm) + expf(sc.z - nm); m2 = nm;
        nm = fmaxf(m3, sc.w); s3 = s3 * expf(m3 - nm) + expf(sc.w - nm); m3 = nm;
    }
    g_m[n * 4 + 0] = m0; g_m[n * 4 + 1] = m1; g_m[n * 4 + 2] = m2; g_m[n * 4 + 3] = m3;
    g_den[n * 4 + 0] = s0; g_den[n * 4 + 1] = s1; g_den[n * 4 + 2] = s2; g_den[n * 4 + 3] = s3;
}

__global__ void agg_k(const int* __restrict__ src, int N) {
    int gt = blockIdx.x * blockDim.x + threadIdx.x;
    int n = gt >> 5, l = gt & 31;
    if (n >= N) return;
    int h = l >> 3;
    float m = g_m[n * 4 + h];
    float inv = 1.0f / (g_den[n * 4 + h] + 1e-16f);
    int b = g_rowptr[n], e = g_rowptr[n + 1];
    float4 acc = make_float4(0.f, 0.f, 0.f, 0.f);
    for (int j = b; j < e; j++) {
        int eid = g_eid[j];
        int s = src[eid];
        float a = expf(g_sc[(size_t)eid * 4 + h] - m) * inv;
        float4 v4 = ((const float4*)g_v)[(size_t)s * DV4 + l];
        float4 ev4 = ((const float4*)g_ev)[(size_t)eid * DV4 + l];
        acc.x += a * (v4.x + ev4.x);
        acc.y += a * (v4.y + ev4.y);
        acc.z += a * (v4.z + ev4.z);
        acc.w += a * (v4.w + ev4.w);
    }
    ((float4*)g_agg)[(size_t)n * DV4 + l] = acc;
}

// ---------------- readout ----------------
__global__ void node_scatter_k(const int* __restrict__ nt, const int* __restrict__ batch, int n32) {
    int i = blockIdx.x * blockDim.x + threadIdx.x;
    if (i >= n32) return;
    int n = i >> 5, c = i & 31;
    if (nt[n] != 0) return;
    int g = batch[n];
    float4 f = ((const float4*)g_feat)[i];
    atomicAdd(&g_gagg[g * DD + c * 4 + 0], f.x);
    atomicAdd(&g_gagg[g * DD + c * 4 + 1], f.y);
    atomicAdd(&g_gagg[g * DD + c * 4 + 2], f.z);
    atomicAdd(&g_gagg[g * DD + c * 4 + 3], f.w);
    if (c == 0) atomicAdd(&g_gcnt[g], 1.0f);
}

__global__ void edge_scatter_k(const int* __restrict__ src, const int* __restrict__ batch, int e32) {
    int i = blockIdx.x * blockDim.x + threadIdx.x;
    if (i >= e32) return;
    int ed = i >> 5, c = i & 31;
    int g = batch[src[ed]];
    float4 f = ((const float4*)g_e)[i];
    atomicAdd(&g_eagg[g * DD + c * 4 + 0], f.x);
    atomicAdd(&g_eagg[g * DD + c * 4 + 1], f.y);
    atomicAdd(&g_eagg[g * DD + c * 4 + 2], f.z);
    atomicAdd(&g_eagg[g * DD + c * 4 + 3], f.w);
    if (c == 0) atomicAdd(&g_ecnt[g], 1.0f);
}

__global__ void final_k(const float* __restrict__ QW1, const float* __restrict__ Qb1,
                        const float* __restrict__ QW2, const float* __restrict__ Qb2,
                        float* __restrict__ out, int A) {
    int g = blockIdx.x;
    int t = threadIdx.x;
    __shared__ float ga[256];
    __shared__ float hh[128];
    __shared__ float lg[128];
    __shared__ float lse_s;
    float ncnt = fmaxf(g_gcnt[g], 1.0f);
    float ecnt = fmaxf(g_ecnt[g], 1.0f);
    if (t < 128) ga[t] = g_gagg[g * DD + t] / ncnt;
    else         ga[t] = g_eagg[g * DD + (t - 128)] / ecnt;
    __syncthreads();
    if (t < 128) {
        float acc = Qb1[t];
        for (int j = 0; j < 256; j++) acc += ga[j] * QW1[j * 128 + t];
        hh[t] = fmaxf(acc, 0.f);
    }
    __syncthreads();
    if (t < A) {
        float acc = Qb2[t];
        for (int j = 0; j < 128; j++) acc += hh[j] * QW2[j * A + t];
        lg[t] = acc;
    }
    __syncthreads();
    if (t == 0) {
        float m = -1e30f;
        for (int i = 0; i < A; i++) m = fmaxf(m, lg[i]);
        float s = 0.f;
        for (int i = 0; i < A; i++) s += expf(lg[i] - m);
        lse_s = logf(s) + m;
    }
    __syncthreads();
    if (t < A) out[g * A + t] = lg[t] - lse_s;
}

// ---------------- host launcher ----------------
extern "C" void kernel_launch(void* const* d_in, const int* in_sizes, int n_in,
                              void* d_out, int out_size) {
    const int*   x         = (const int*)d_in[0];
    const int*   node_type = (const int*)d_in[1];
    const int*   batch     = (const int*)d_in[2];
    const int*   eix       = (const int*)d_in[3];
    const int*   flow      = (const int*)d_in[4];
    const int*   pos       = (const int*)d_in[5];
    const int*   blk       = (const int*)d_in[6];
    const float* emb       = (const float*)d_in[8];
    const float* fe        = (const float*)d_in[9];
    const float* pe        = (const float*)d_in[10];
    const float* be        = (const float*)d_in[11];
    const float* Wq        = (const float*)d_in[12];
    const float* Wk        = (const float*)d_in[13];
    const float* Wv        = (const float*)d_in[14];
    const float* Wek       = (const float*)d_in[15];
    const float* Wev       = (const float*)d_in[16];
    const float* Wo        = (const float*)d_in[17];
    const float* Weu       = (const float*)d_in[18];
    const float* QW1       = (const float*)d_in[19];
    const float* Qb1       = (const float*)d_in[20];
    const float* QW2       = (const float*)d_in[21];
    const float* Qb2       = (const float*)d_in[22];

    int N = in_sizes[0];
    int E = in_sizes[4];
    int L = in_sizes[12] / (128 * 128);
    int A = in_sizes[22];
    const int* src = eix;
    const int* dst = eix + E;

    float *p_feat, *p_q, *p_k, *p_v, *p_agg, *p_P1, *p_P2, *p_e, *p_ev;
    float *p_gagg, *p_eagg, *p_gcnt, *p_ecnt;
    int *p_cnt;
    cudaGetSymbolAddress((void**)&p_feat, g_feat);
    cudaGetSymbolAddress((void**)&p_q, g_q);
    cudaGetSymbolAddress((void**)&p_k, g_k);
    cudaGetSymbolAddress((void**)&p_v, g_v);
    cudaGetSymbolAddress((void**)&p_agg, g_agg);
    cudaGetSymbolAddress((void**)&p_P1, g_P1);
    cudaGetSymbolAddress((void**)&p_P2, g_P2);
    cudaGetSymbolAddress((void**)&p_e, g_e);
    cudaGetSymbolAddress((void**)&p_ev, g_ev);
    cudaGetSymbolAddress((void**)&p_cnt, g_cnt);
    cudaGetSymbolAddress((void**)&p_gagg, g_gagg);
    cudaGetSymbolAddress((void**)&p_eagg, g_eagg);
    cudaGetSymbolAddress((void**)&p_gcnt, g_gcnt);
    cudaGetSymbolAddress((void**)&p_ecnt, g_ecnt);

    cudaFuncSetAttribute(gemm_node6_k, cudaFuncAttributeMaxDynamicSharedMemorySize, SMEM_DB);
    cudaFuncSetAttribute(gemm_edge3_k, cudaFuncAttributeMaxDynamicSharedMemorySize, SMEM_DB);
    cudaFuncSetAttribute(gemm_epi_k,   cudaFuncAttributeMaxDynamicSharedMemorySize, SMEM_SB);

    const int T = 256;
    int gN = ceil_div(N, 128), gE = ceil_div(E, 128);

    // launches: 1 memset, 2 embed, 3 edge_enc, 4 hist, 5 scan, 6 node6(L0) <- ncu
    cudaMemsetAsync(p_cnt, 0, (size_t)N * 4);
    embed_k<<<ceil_div(N * 32, T), T>>>(x, emb, N * 32);
    edge_enc_k<<<ceil_div(E * 32, T), T>>>(flow, pos, blk, src, dst, fe, pe, be, E * 32);
    hist_k<<<ceil_div(E, T), T>>>(dst, E);
    scan_k<<<1, 1024>>>(N);   // also re-zeroes g_cnt
    gemm_node6_k<<<gN, 512, SMEM_DB>>>(p_agg, 0, p_feat,
                                       Wq, Wk, Wv, Weu, Weu + 16384,
                                       p_q, p_k, p_v, p_P1, p_P2, N, 0);
    fill_k<<<ceil_div(E, T), T>>>(dst, E);

    for (int l = 0; l < L; l++) {
        const float* wek = Wek + (size_t)l * 16384;
        const float* wev = Wev + (size_t)l * 16384;
        const float* weu = Weu + (size_t)l * 49152;
        if (l > 0) {
            // pre-pass: feat = relu(feat + agg@Wo[l-1]), then q,k,v,P1,P2 of layer l
            gemm_node6_k<<<gN, 512, SMEM_DB>>>(p_agg, Wo + (size_t)(l - 1) * 16384, p_feat,
                                               Wq + (size_t)l * 16384, Wk + (size_t)l * 16384,
                                               Wv + (size_t)l * 16384, weu, weu + 16384,
                                               p_q, p_k, p_v, p_P1, p_P2, N, 1);
        }
        gemm_edge3_k<<<gE, 512, SMEM_DB>>>(p_e, wek, wev, weu + 32768,
                                           p_ev, p_e, p_P1, p_P2, src, dst, E);
        stats_k<<<ceil_div(N, T), T>>>(N);
        agg_k<<<ceil_div(N * 32, T), T>>>(src, N);
    }
    // final feature update
    gemm_epi_k<<<gN, 512, SMEM_SB>>>(p_agg, Wo + (size_t)(L - 1) * 16384, p_feat, p_feat, N);

    // readout
    cudaMemsetAsync(p_gagg, 0, (size_t)GMAX * DD * 4);
    cudaMemsetAsync(p_eagg, 0, (size_t)GMAX * DD * 4);
    cudaMemsetAsync(p_gcnt, 0, (size_t)GMAX * 4);
    cudaMemsetAsync(p_ecnt, 0, (size_t)GMAX * 4);
    node_scatter_k<<<ceil_div(N * 32, T), T>>>(node_type, batch, N * 32);
    edge_scatter_k<<<ceil_div(E * 32, T), T>>>(src, batch, E * 32);
    final_k<<<GMAX, T>>>(QW1, Qb1, QW2, Qb2, (float*)d_out, A);
}